// round 1
// baseline (speedup 1.0000x reference)
#include <cuda_runtime.h>
#include <math.h>

#define SQ   3072
#define HIDD 1152
#define NHD  16
#define HDIM 72
#define MLPD 4304
#define T3   3456
#define EPSLN 1e-5f

// ---------------- scratch (allocation-free: __device__ globals) ----------------
__device__ float g_h[SQ * HIDD];
__device__ float g_qkv[SQ * T3];
__device__ float g_attnout[SQ * HIDD];
__device__ float g_y1[SQ * HIDD];
__device__ float g_mlp[(size_t)SQ * MLPD];
__device__ float g_scores[(size_t)NHD * SQ * SQ];
__device__ int   g_seg[SQ];

// ---------------- helpers ----------------
__device__ __forceinline__ float gelu_tanh(float x) {
    float x3 = x * x * x;
    return 0.5f * x * (1.0f + tanhf(0.7978845608028654f * (x + 0.044715f * x3)));
}

// ---------------- layernorm ----------------
__global__ void ln_kernel(const float* __restrict__ x,
                          const float* __restrict__ g,
                          const float* __restrict__ b,
                          float* __restrict__ out) {
    int row = blockIdx.x;
    const float* xr = x + (size_t)row * HIDD;
    float s1 = 0.f, s2 = 0.f;
    for (int i = threadIdx.x; i < HIDD; i += blockDim.x) {
        float v = xr[i];
        s1 += v; s2 += v * v;
    }
    __shared__ float sh1[8], sh2[8];
    #pragma unroll
    for (int o = 16; o; o >>= 1) {
        s1 += __shfl_xor_sync(0xffffffffu, s1, o);
        s2 += __shfl_xor_sync(0xffffffffu, s2, o);
    }
    int w = threadIdx.x >> 5, l = threadIdx.x & 31;
    if (l == 0) { sh1[w] = s1; sh2[w] = s2; }
    __syncthreads();
    if (w == 0) {
        s1 = (l < 8) ? sh1[l] : 0.f;
        s2 = (l < 8) ? sh2[l] : 0.f;
        #pragma unroll
        for (int o = 4; o; o >>= 1) {
            s1 += __shfl_xor_sync(0xffffffffu, s1, o);
            s2 += __shfl_xor_sync(0xffffffffu, s2, o);
        }
        if (l == 0) { sh1[0] = s1; sh2[0] = s2; }
    }
    __syncthreads();
    float mu = sh1[0] * (1.0f / HIDD);
    float var = sh2[0] * (1.0f / HIDD) - mu * mu;
    float rs = rsqrtf(var + EPSLN);
    float* orow = out + (size_t)row * HIDD;
    for (int i = threadIdx.x; i < HIDD; i += blockDim.x) {
        orow[i] = (xr[i] - mu) * rs * g[i] + b[i];
    }
}

// ---------------- segment ids ----------------
__global__ void seg_kernel(const int* __restrict__ off, int n, int* __restrict__ seg) {
    int t = blockIdx.x * blockDim.x + threadIdx.x;
    if (t >= SQ) return;
    int s = 0;
    for (int i = 1; i < n; i++)
        if (t >= off[i]) s = i;
    seg[t] = s;
}

// ---------------- RoPE on q and k (in-place in qkv) ----------------
__global__ void rope_kernel(float* __restrict__ qkv, const float* __restrict__ fc) {
    int idx = blockIdx.x * blockDim.x + threadIdx.x;
    const int NP = HDIM / 2;              // 36
    if (idx >= SQ * NHD * NP) return;
    int p = idx % NP;
    int h = (idx / NP) % NHD;
    int s = idx / (NP * NHD);
    float c  = fc[s * HDIM + 2 * p];
    float sn = fc[s * HDIM + 2 * p + 1];
    size_t base = (size_t)s * T3 + h * HDIM + 2 * p;
    float a = qkv[base], b = qkv[base + 1];
    qkv[base]     = a * c - b * sn;
    qkv[base + 1] = a * sn + b * c;
    base += HIDD;                          // k
    a = qkv[base]; b = qkv[base + 1];
    qkv[base]     = a * c - b * sn;
    qkv[base + 1] = a * sn + b * c;
}

// ---------------- row softmax (register-resident, S=3072, 256 thr) ----------------
__global__ void softmax_kernel(float* __restrict__ p) {
    float* pr = p + (size_t)blockIdx.x * SQ;
    int t = threadIdx.x;
    float v[12];
    float m = -1e30f;
    #pragma unroll
    for (int i = 0; i < 12; i++) {
        v[i] = pr[t + i * 256];
        m = fmaxf(m, v[i]);
    }
    __shared__ float sm[8];
    #pragma unroll
    for (int o = 16; o; o >>= 1) m = fmaxf(m, __shfl_xor_sync(0xffffffffu, m, o));
    int w = t >> 5, l = t & 31;
    if (l == 0) sm[w] = m;
    __syncthreads();
    if (w == 0) {
        m = (l < 8) ? sm[l] : -1e30f;
        #pragma unroll
        for (int o = 4; o; o >>= 1) m = fmaxf(m, __shfl_xor_sync(0xffffffffu, m, o));
        if (l == 0) sm[0] = m;
    }
    __syncthreads();
    m = sm[0];
    float sum = 0.f;
    #pragma unroll
    for (int i = 0; i < 12; i++) {
        v[i] = __expf(v[i] - m);
        sum += v[i];
    }
    __syncthreads();
    #pragma unroll
    for (int o = 16; o; o >>= 1) sum += __shfl_xor_sync(0xffffffffu, sum, o);
    if (l == 0) sm[w] = sum;
    __syncthreads();
    if (w == 0) {
        sum = (l < 8) ? sm[l] : 0.f;
        #pragma unroll
        for (int o = 4; o; o >>= 1) sum += __shfl_xor_sync(0xffffffffu, sum, o);
        if (l == 0) sm[0] = sum;
    }
    __syncthreads();
    float inv = 1.0f / sm[0];
    #pragma unroll
    for (int i = 0; i < 12; i++) pr[t + i * 256] = v[i] * inv;
}

// ---------------- generic batched SGEMM ----------------
// C[b] = epilogue( A[b](MxK) * B[b](KxN) )
// TRANSB: B element (k,n) at B[n*ldb + k]
// MODE 0: +bias (nullable)
// MODE 1: gelu(+bias)
// MODE 2: alpha*acc + (seg[row]==seg[col] ? 1 : 0)
// MODE 3: +bias + resid[row*ldr+col]
// Requirements: M % 128 == 0, K % 8 == 0, N arbitrary (guarded), all float4-aligned.
template <bool TRANSB, int MODE>
__global__ void __launch_bounds__(256)
sgemm_kernel(int M, int N, int K,
             const float* __restrict__ A, int lda, long sA,
             const float* __restrict__ B, int ldb, long sB,
             float* __restrict__ C, int ldc, long sC,
             const float* __restrict__ bias,
             const float* __restrict__ resid, int ldr,
             const int* __restrict__ seg, float alpha) {
    A += (long)blockIdx.z * sA;
    B += (long)blockIdx.z * sB;
    C += (long)blockIdx.z * sC;

    __shared__ float As[8][128];
    __shared__ float Bs[8][128];

    const int tid = threadIdx.x;
    const int m0 = blockIdx.y * 128;
    const int n0 = blockIdx.x * 128;

    const int arow = tid >> 1;            // 0..127
    const int acol = (tid & 1) * 4;       // 0 or 4
    const int ty = tid >> 4;              // 0..15
    const int tx = tid & 15;              // 0..15

    float acc[8][8];
    #pragma unroll
    for (int i = 0; i < 8; i++)
        #pragma unroll
        for (int j = 0; j < 8; j++) acc[i][j] = 0.f;

    for (int k0 = 0; k0 < K; k0 += 8) {
        // A tile: always in bounds (M%128==0, K%8==0)
        float4 av = *(const float4*)(A + (long)(m0 + arow) * lda + k0 + acol);

        if (!TRANSB) {
            int brow = tid >> 5;           // 0..7
            int bcol = (tid & 31) * 4;     // 0..124
            int n = n0 + bcol;
            float4 bv;
            if (n + 3 < N) {
                bv = *(const float4*)(B + (long)(k0 + brow) * ldb + n);
            } else {
                const float* bp = B + (long)(k0 + brow) * ldb;
                bv.x = (n + 0 < N) ? bp[n + 0] : 0.f;
                bv.y = (n + 1 < N) ? bp[n + 1] : 0.f;
                bv.z = (n + 2 < N) ? bp[n + 2] : 0.f;
                bv.w = (n + 3 < N) ? bp[n + 3] : 0.f;
            }
            *(float4*)&Bs[brow][bcol] = bv;
        } else {
            int bn = tid >> 1;             // 0..127
            int bk = (tid & 1) * 4;        // 0 or 4
            float4 bv = make_float4(0.f, 0.f, 0.f, 0.f);
            if (n0 + bn < N)
                bv = *(const float4*)(B + (long)(n0 + bn) * ldb + k0 + bk);
            Bs[bk + 0][bn] = bv.x;
            Bs[bk + 1][bn] = bv.y;
            Bs[bk + 2][bn] = bv.z;
            Bs[bk + 3][bn] = bv.w;
        }
        As[acol + 0][arow] = av.x;
        As[acol + 1][arow] = av.y;
        As[acol + 2][arow] = av.z;
        As[acol + 3][arow] = av.w;
        __syncthreads();

        #pragma unroll
        for (int k = 0; k < 8; k++) {
            float4 a0 = *(const float4*)&As[k][ty * 8];
            float4 a1 = *(const float4*)&As[k][ty * 8 + 4];
            float4 b0 = *(const float4*)&Bs[k][tx * 8];
            float4 b1 = *(const float4*)&Bs[k][tx * 8 + 4];
            float ar[8] = {a0.x, a0.y, a0.z, a0.w, a1.x, a1.y, a1.z, a1.w};
            float br[8] = {b0.x, b0.y, b0.z, b0.w, b1.x, b1.y, b1.z, b1.w};
            #pragma unroll
            for (int i = 0; i < 8; i++)
                #pragma unroll
                for (int j = 0; j < 8; j++)
                    acc[i][j] = fmaf(ar[i], br[j], acc[i][j]);
        }
        __syncthreads();
    }

    // epilogue
    #pragma unroll
    for (int i = 0; i < 8; i++) {
        int row = m0 + ty * 8 + i;
        int sr = 0;
        if (MODE == 2) sr = seg[row];
        float* crow = C + (long)row * ldc;
        #pragma unroll
        for (int j = 0; j < 8; j++) {
            int col = n0 + tx * 8 + j;
            if (col < N) {
                float v = acc[i][j];
                if (MODE == 0) {
                    if (bias) v += bias[col];
                } else if (MODE == 1) {
                    v = gelu_tanh(v + bias[col]);
                } else if (MODE == 2) {
                    v = alpha * v + ((sr == seg[col]) ? 1.0f : 0.0f);
                } else if (MODE == 3) {
                    v += bias[col] + resid[(long)row * ldr + col];
                }
                crow[col] = v;
            }
        }
    }
}

// ---------------- launcher ----------------
extern "C" void kernel_launch(void* const* d_in, const int* in_sizes, int n_in,
                              void* d_out, int out_size) {
    const float* x      = (const float*)d_in[0];
    const int*   offs   = (const int*)d_in[1];
    const float* fc     = (const float*)d_in[2];
    const float* ln0_g  = (const float*)d_in[3];
    const float* ln0_b  = (const float*)d_in[4];
    const float* wqkv_w = (const float*)d_in[5];
    const float* wqkv_b = (const float*)d_in[6];
    const float* wo_w   = (const float*)d_in[7];
    const float* wo_b   = (const float*)d_in[8];
    const float* ln1_g  = (const float*)d_in[9];
    const float* ln1_b  = (const float*)d_in[10];
    const float* w1     = (const float*)d_in[11];
    const float* b1     = (const float*)d_in[12];
    const float* w2     = (const float*)d_in[13];
    const float* b2     = (const float*)d_in[14];
    float* out = (float*)d_out;

    float *h, *qkv, *att, *y1, *mlp, *scores;
    int* seg;
    cudaGetSymbolAddress((void**)&h, g_h);
    cudaGetSymbolAddress((void**)&qkv, g_qkv);
    cudaGetSymbolAddress((void**)&att, g_attnout);
    cudaGetSymbolAddress((void**)&y1, g_y1);
    cudaGetSymbolAddress((void**)&mlp, g_mlp);
    cudaGetSymbolAddress((void**)&scores, g_scores);
    cudaGetSymbolAddress((void**)&seg, g_seg);

    const float alpha = 0.11785113019775793f; // 1/sqrt(72)
    int n_off = in_sizes[1];

    // 1. LN0
    ln_kernel<<<SQ, 256>>>(x, ln0_g, ln0_b, h);

    // 2. QKV = h @ wqkv_w + b   (3072 x 3456)
    sgemm_kernel<false, 0><<<dim3(T3 / 128, SQ / 128, 1), 256>>>(
        SQ, T3, HIDD, h, HIDD, 0, wqkv_w, T3, 0, qkv, T3, 0,
        wqkv_b, nullptr, 0, nullptr, 0.f);

    // 3. segment ids
    seg_kernel<<<(SQ + 255) / 256, 256>>>(offs, n_off, seg);

    // 4. RoPE on q,k
    {
        int total = SQ * NHD * (HDIM / 2);
        rope_kernel<<<(total + 255) / 256, 256>>>(qkv, fc);
    }

    // 5. scores[h] = alpha * Q K^T + segbias   (per head: 3072x3072, K=72)
    sgemm_kernel<true, 2><<<dim3(SQ / 128, SQ / 128, NHD), 256>>>(
        SQ, SQ, HDIM,
        qkv, T3, (long)HDIM,                 // Q, head stride 72
        qkv + HIDD, T3, (long)HDIM,          // K, head stride 72
        scores, SQ, (long)SQ * SQ,
        nullptr, nullptr, 0, seg, alpha);

    // 6. softmax rows (16*3072 rows of 3072)
    softmax_kernel<<<NHD * SQ, 256>>>(scores);

    // 7. attn_out[h] = P V   (3072x72, K=3072)
    sgemm_kernel<false, 0><<<dim3(1, SQ / 128, NHD), 256>>>(
        SQ, HDIM, SQ,
        scores, SQ, (long)SQ * SQ,
        qkv + 2 * HIDD, T3, (long)HDIM,
        att, HIDD, (long)HDIM,
        nullptr, nullptr, 0, nullptr, 0.f);

    // 8. y1 = x + attn_out @ wo_w + wo_b
    sgemm_kernel<false, 3><<<dim3(HIDD / 128, SQ / 128, 1), 256>>>(
        SQ, HIDD, HIDD, att, HIDD, 0, wo_w, HIDD, 0, y1, HIDD, 0,
        wo_b, x, HIDD, nullptr, 0.f);

    // 9. LN1
    ln_kernel<<<SQ, 256>>>(y1, ln1_g, ln1_b, h);

    // 10. mlp = gelu(h @ w1 + b1)   (3072 x 4304)
    sgemm_kernel<false, 1><<<dim3((MLPD + 127) / 128, SQ / 128, 1), 256>>>(
        SQ, MLPD, HIDD, h, HIDD, 0, w1, MLPD, 0, mlp, MLPD, 0,
        b1, nullptr, 0, nullptr, 0.f);

    // 11. out = y1 + mlp @ w2 + b2
    sgemm_kernel<false, 3><<<dim3(HIDD / 128, SQ / 128, 1), 256>>>(
        SQ, HIDD, MLPD, mlp, MLPD, 0, w2, HIDD, 0, out, HIDD, 0,
        b2, y1, HIDD, nullptr, 0.f);
}

// round 4
// speedup vs baseline: 1.8481x; 1.8481x over previous
#include <cuda_runtime.h>
#include <cuda_bf16.h>
#include <math.h>
#include <stdint.h>

#define SQ   3072
#define HIDD 1152
#define NHD  16
#define HDIM 72
#define MLPD 4304
#define T3   3456
#define EPSLN 1e-5f

// ---------------- scratch (allocation-free: __device__ globals) ----------------
__device__ float g_h[SQ * HIDD];
__device__ float g_qkv[SQ * T3];
__device__ float g_attnout[SQ * HIDD];
__device__ float g_y1[SQ * HIDD];
__device__ float g_mlp[(size_t)SQ * MLPD];
__device__ float g_scores[(size_t)NHD * SQ * SQ];
__device__ int   g_seg[SQ];

// ---------------- helpers ----------------
__device__ __forceinline__ uint32_t smem_u32(const void* p) {
    uint32_t a;
    asm("{ .reg .u64 t; cvta.to.shared.u64 t, %1; cvt.u32.u64 %0, t; }" : "=r"(a) : "l"(p));
    return a;
}

__device__ __forceinline__ void ldsm4(uint32_t r[4], uint32_t a) {
    asm volatile("ldmatrix.sync.aligned.m8n8.x4.shared.b16 {%0,%1,%2,%3}, [%4];"
                 : "=r"(r[0]), "=r"(r[1]), "=r"(r[2]), "=r"(r[3]) : "r"(a));
}

__device__ __forceinline__ void mma16816(float d[4], const uint32_t a[4], const uint32_t b[2]) {
    asm volatile(
        "mma.sync.aligned.m16n8k16.row.col.f32.bf16.bf16.f32 "
        "{%0,%1,%2,%3}, {%4,%5,%6,%7}, {%8,%9}, {%0,%1,%2,%3};"
        : "+f"(d[0]), "+f"(d[1]), "+f"(d[2]), "+f"(d[3])
        : "r"(a[0]), "r"(a[1]), "r"(a[2]), "r"(a[3]), "r"(b[0]), "r"(b[1]));
}

__device__ __forceinline__ void split_bf(float f, unsigned short& h, unsigned short& l) {
    __nv_bfloat16 hb = __float2bfloat16(f);
    float r = f - __bfloat162float(hb);
    __nv_bfloat16 lb = __float2bfloat16(r);
    h = __bfloat16_as_ushort(hb);
    l = __bfloat16_as_ushort(lb);
}

__device__ __forceinline__ float gelu_tanh(float x) {
    float x3 = x * x * x;
    return 0.5f * x * (1.0f + tanhf(0.7978845608028654f * (x + 0.044715f * x3)));
}

// ================= bf16-split tensor-core GEMM (mma.sync path) =================
// D[m][n] = epilogue( sum_k A[m][k] * Bsm[n][k] ), per batch z.
//   TRANSB=false: Bsm[n][k] = B[k*ldb + n]
//   TRANSB=true : Bsm[n][k] = B[n*ldb + k]
// MODE 0: +bias (nullable)   MODE 1: gelu(+bias)
// MODE 2: alpha*acc + (seg[row]==seg[col])   MODE 3: +bias + resid
// Tile: 128x128, BK=32, 8 warps (warp tile 64x32).
// smem per stage: Ah,Al,Bh,Bl tiles, each 128 rows x 80B = 10240B -> 40960B; 2 stages.
#define ROWB   80
#define TILEB  (128 * ROWB)
#define STAGEB (4 * TILEB)
#define GM_SMEM (2 * STAGEB)

template <bool TRANSB, int MODE>
__global__ void __launch_bounds__(256)
gemm_mma(int N, int K,
         const float* __restrict__ A, int lda, long sA,
         const float* __restrict__ B, int ldb, long sB,
         float* __restrict__ C, int ldc, long sC,
         const float* __restrict__ bias,
         const float* __restrict__ resid, int ldr,
         const int* __restrict__ seg, float alpha) {
    extern __shared__ char smbuf[];
    const int tid = threadIdx.x;
    const int lane = tid & 31, wid = tid >> 5;
    const int wm = wid & 1, wn = wid >> 1;      // warps: 2 x 4 (m x n)
    const int m0 = blockIdx.y * 128;
    const int n0 = blockIdx.x * 128;

    A += (long)blockIdx.z * sA;
    B += (long)blockIdx.z * sB;
    C += (long)blockIdx.z * sC;

    // loader mappings
    const int ar  = tid >> 1;           // 0..127 rows
    const int akq = (tid & 1) * 16;     // 0 or 16 (k offset, 16 floats per thread)
    const int bn  = tid & 127;          // TRANSB=false: fixed n per thread
    const int bkh = (tid >> 7) * 16;    // k half

    float4 avA[4];
    float4 avB[4];
    float  bvB[16];

    const int nc = (K + 31) >> 5;

    // ---- LDG for chunk c into registers ----
    #define LDG_CHUNK(c_)  do {                                                   \
        int k0_ = (c_) * 32;                                                      \
        const float* ap_ = A + (size_t)(m0 + ar) * lda + k0_ + akq;               \
        _Pragma("unroll")                                                         \
        for (int j = 0; j < 4; j++)                                               \
            avA[j] = (k0_ + akq + 4 * j < K) ? *(const float4*)(ap_ + 4 * j)      \
                                             : make_float4(0.f, 0.f, 0.f, 0.f);   \
        if (TRANSB) {                                                             \
            const float* bp_ = B + (size_t)(n0 + ar) * ldb + k0_ + akq;           \
            bool ok_ = (n0 + ar) < N;                                             \
            _Pragma("unroll")                                                     \
            for (int j = 0; j < 4; j++)                                           \
                avB[j] = (ok_ && k0_ + akq + 4 * j < K)                           \
                             ? *(const float4*)(bp_ + 4 * j)                      \
                             : make_float4(0.f, 0.f, 0.f, 0.f);                   \
        } else {                                                                  \
            bool ok_ = (n0 + bn) < N;                                             \
            _Pragma("unroll")                                                     \
            for (int j = 0; j < 16; j++)                                          \
                bvB[j] = (ok_ && k0_ + bkh + j < K)                               \
                             ? B[(size_t)(k0_ + bkh + j) * ldb + n0 + bn] : 0.f;  \
        }                                                                         \
    } while (0)

    // ---- convert + STS into stage s ----
    #define STS_CHUNK(s_)  do {                                                   \
        char* st_ = smbuf + (s_) * STAGEB;                                        \
        _Pragma("unroll")                                                         \
        for (int j = 0; j < 4; j++) {                                             \
            unsigned short h0, h1, h2, h3, l0, l1, l2, l3;                        \
            split_bf(avA[j].x, h0, l0); split_bf(avA[j].y, h1, l1);               \
            split_bf(avA[j].z, h2, l2); split_bf(avA[j].w, h3, l3);               \
            uint2 hp = make_uint2((uint32_t)h0 | ((uint32_t)h1 << 16),            \
                                  (uint32_t)h2 | ((uint32_t)h3 << 16));           \
            uint2 lp = make_uint2((uint32_t)l0 | ((uint32_t)l1 << 16),            \
                                  (uint32_t)l2 | ((uint32_t)l3 << 16));           \
            uint32_t off = (uint32_t)ar * ROWB + (uint32_t)(akq + 4 * j) * 2u;    \
            *(uint2*)(st_ + off) = hp;                                            \
            *(uint2*)(st_ + TILEB + off) = lp;                                    \
        }                                                                         \
        if (TRANSB) {                                                             \
            _Pragma("unroll")                                                     \
            for (int j = 0; j < 4; j++) {                                         \
                unsigned short h0, h1, h2, h3, l0, l1, l2, l3;                    \
                split_bf(avB[j].x, h0, l0); split_bf(avB[j].y, h1, l1);           \
                split_bf(avB[j].z, h2, l2); split_bf(avB[j].w, h3, l3);           \
                uint2 hp = make_uint2((uint32_t)h0 | ((uint32_t)h1 << 16),        \
                                      (uint32_t)h2 | ((uint32_t)h3 << 16));       \
                uint2 lp = make_uint2((uint32_t)l0 | ((uint32_t)l1 << 16),        \
                                      (uint32_t)l2 | ((uint32_t)l3 << 16));       \
                uint32_t off = (uint32_t)ar * ROWB + (uint32_t)(akq + 4 * j) * 2u;\
                *(uint2*)(st_ + 2 * TILEB + off) = hp;                            \
                *(uint2*)(st_ + 3 * TILEB + off) = lp;                            \
            }                                                                     \
        } else {                                                                  \
            _Pragma("unroll")                                                     \
            for (int j = 0; j < 8; j++) {                                         \
                unsigned short h0, h1, l0, l1;                                    \
                split_bf(bvB[2 * j], h0, l0);                                     \
                split_bf(bvB[2 * j + 1], h1, l1);                                 \
                uint32_t hp = (uint32_t)h0 | ((uint32_t)h1 << 16);                \
                uint32_t lp = (uint32_t)l0 | ((uint32_t)l1 << 16);                \
                uint32_t off = (uint32_t)bn * ROWB + (uint32_t)(bkh + 2 * j) * 2u;\
                *(uint32_t*)(st_ + 2 * TILEB + off) = hp;                         \
                *(uint32_t*)(st_ + 3 * TILEB + off) = lp;                         \
            }                                                                     \
        }                                                                         \
    } while (0)

    float acc[4][4][4];
    #pragma unroll
    for (int mi = 0; mi < 4; mi++)
        #pragma unroll
        for (int ni = 0; ni < 4; ni++)
            #pragma unroll
            for (int e = 0; e < 4; e++) acc[mi][ni][e] = 0.f;

    const uint32_t sbase = smem_u32(smbuf);
    const uint32_t aoff = (uint32_t)(wm * 64 + (lane & 15)) * ROWB + (lane >> 4) * 16;
    const uint32_t boff = (uint32_t)(wn * 32 + ((lane >> 4) << 3) + (lane & 7)) * ROWB
                          + ((lane >> 3) & 1) * 16;

    LDG_CHUNK(0);
    STS_CHUNK(0);

    for (int c = 0; c < nc; c++) {
        __syncthreads();
        if (c + 1 < nc) LDG_CHUNK(c + 1);

        const uint32_t stb = sbase + (uint32_t)(c & 1) * STAGEB;
        #pragma unroll
        for (int kk = 0; kk < 2; kk++) {
            uint32_t ah[4][4], al[4][4], bh[4][2], bl[4][2];
            #pragma unroll
            for (int mi = 0; mi < 4; mi++) {
                uint32_t base = stb + aoff + mi * 16 * ROWB + kk * 32;
                ldsm4(ah[mi], base);
                ldsm4(al[mi], base + TILEB);
            }
            #pragma unroll
            for (int nj = 0; nj < 2; nj++) {
                uint32_t t[4];
                uint32_t base = stb + 2 * TILEB + boff + nj * 16 * ROWB + kk * 32;
                ldsm4(t, base);
                bh[2 * nj][0] = t[0]; bh[2 * nj][1] = t[1];
                bh[2 * nj + 1][0] = t[2]; bh[2 * nj + 1][1] = t[3];
                ldsm4(t, base + TILEB);
                bl[2 * nj][0] = t[0]; bl[2 * nj][1] = t[1];
                bl[2 * nj + 1][0] = t[2]; bl[2 * nj + 1][1] = t[3];
            }
            #pragma unroll
            for (int mi = 0; mi < 4; mi++)
                #pragma unroll
                for (int ni = 0; ni < 4; ni++)
                    mma16816(acc[mi][ni], ah[mi], bh[ni]);
            #pragma unroll
            for (int mi = 0; mi < 4; mi++)
                #pragma unroll
                for (int ni = 0; ni < 4; ni++)
                    mma16816(acc[mi][ni], ah[mi], bl[ni]);
            #pragma unroll
            for (int mi = 0; mi < 4; mi++)
                #pragma unroll
                for (int ni = 0; ni < 4; ni++)
                    mma16816(acc[mi][ni], al[mi], bh[ni]);
        }
        if (c + 1 < nc) STS_CHUNK((c + 1) & 1);
    }

    // ---- epilogue: direct float2 stores ----
    const int tr = lane >> 2;
    const int tc2 = (lane & 3) * 2;
    #pragma unroll
    for (int mi = 0; mi < 4; mi++) {
        #pragma unroll
        for (int h = 0; h < 2; h++) {
            int row = m0 + wm * 64 + mi * 16 + h * 8 + tr;
            int sr = 0;
            if (MODE == 2) sr = seg[row];
            float* crow = C + (size_t)row * ldc;
            const float* rrow = (MODE == 3) ? resid + (size_t)row * ldr : nullptr;
            #pragma unroll
            for (int ni = 0; ni < 4; ni++) {
                int col = n0 + wn * 32 + ni * 8 + tc2;
                if (col < N) {
                    float v0 = acc[mi][ni][2 * h];
                    float v1 = acc[mi][ni][2 * h + 1];
                    if (MODE == 0) {
                        if (bias) { v0 += bias[col]; v1 += bias[col + 1]; }
                    } else if (MODE == 1) {
                        v0 = gelu_tanh(v0 + bias[col]);
                        v1 = gelu_tanh(v1 + bias[col + 1]);
                    } else if (MODE == 2) {
                        v0 = alpha * v0 + ((sr == seg[col]) ? 1.0f : 0.0f);
                        v1 = alpha * v1 + ((sr == seg[col + 1]) ? 1.0f : 0.0f);
                    } else if (MODE == 3) {
                        v0 += bias[col] + rrow[col];
                        v1 += bias[col + 1] + rrow[col + 1];
                    }
                    *(float2*)(crow + col) = make_float2(v0, v1);
                }
            }
        }
    }
    #undef LDG_CHUNK
    #undef STS_CHUNK
}

// ---------------- layernorm ----------------
__global__ void ln_kernel(const float* __restrict__ x,
                          const float* __restrict__ g,
                          const float* __restrict__ b,
                          float* __restrict__ out) {
    int row = blockIdx.x;
    const float* xr = x + (size_t)row * HIDD;
    float s1 = 0.f, s2 = 0.f;
    for (int i = threadIdx.x; i < HIDD; i += blockDim.x) {
        float v = xr[i];
        s1 += v; s2 += v * v;
    }
    __shared__ float sh1[8], sh2[8];
    #pragma unroll
    for (int o = 16; o; o >>= 1) {
        s1 += __shfl_xor_sync(0xffffffffu, s1, o);
        s2 += __shfl_xor_sync(0xffffffffu, s2, o);
    }
    int w = threadIdx.x >> 5, l = threadIdx.x & 31;
    if (l == 0) { sh1[w] = s1; sh2[w] = s2; }
    __syncthreads();
    if (w == 0) {
        s1 = (l < 8) ? sh1[l] : 0.f;
        s2 = (l < 8) ? sh2[l] : 0.f;
        #pragma unroll
        for (int o = 4; o; o >>= 1) {
            s1 += __shfl_xor_sync(0xffffffffu, s1, o);
            s2 += __shfl_xor_sync(0xffffffffu, s2, o);
        }
        if (l == 0) { sh1[0] = s1; sh2[0] = s2; }
    }
    __syncthreads();
    float mu = sh1[0] * (1.0f / HIDD);
    float var = sh2[0] * (1.0f / HIDD) - mu * mu;
    float rs = rsqrtf(var + EPSLN);
    float* orow = out + (size_t)row * HIDD;
    for (int i = threadIdx.x; i < HIDD; i += blockDim.x) {
        orow[i] = (xr[i] - mu) * rs * g[i] + b[i];
    }
}

// ---------------- segment ids ----------------
__global__ void seg_kernel(const int* __restrict__ off, int n, int* __restrict__ seg) {
    int t = blockIdx.x * blockDim.x + threadIdx.x;
    if (t >= SQ) return;
    int s = 0;
    for (int i = 1; i < n; i++)
        if (t >= off[i]) s = i;
    seg[t] = s;
}

// ---------------- RoPE on q and k (in-place in qkv) ----------------
__global__ void rope_kernel(float* __restrict__ qkv, const float* __restrict__ fc) {
    int idx = blockIdx.x * blockDim.x + threadIdx.x;
    const int NP = HDIM / 2;
    if (idx >= SQ * NHD * NP) return;
    int p = idx % NP;
    int h = (idx / NP) % NHD;
    int s = idx / (NP * NHD);
    float c  = fc[s * HDIM + 2 * p];
    float sn = fc[s * HDIM + 2 * p + 1];
    size_t base = (size_t)s * T3 + h * HDIM + 2 * p;
    float a = qkv[base], b = qkv[base + 1];
    qkv[base]     = a * c - b * sn;
    qkv[base + 1] = a * sn + b * c;
    base += HIDD;
    a = qkv[base]; b = qkv[base + 1];
    qkv[base]     = a * c - b * sn;
    qkv[base + 1] = a * sn + b * c;
}

// ---------------- row softmax (register-resident, S=3072, 256 thr) ----------------
__global__ void softmax_kernel(float* __restrict__ p) {
    float* pr = p + (size_t)blockIdx.x * SQ;
    int t = threadIdx.x;
    float v[12];
    float m = -1e30f;
    #pragma unroll
    for (int i = 0; i < 12; i++) {
        v[i] = pr[t + i * 256];
        m = fmaxf(m, v[i]);
    }
    __shared__ float sm[8];
    #pragma unroll
    for (int o = 16; o; o >>= 1) m = fmaxf(m, __shfl_xor_sync(0xffffffffu, m, o));
    int w = t >> 5, l = t & 31;
    if (l == 0) sm[w] = m;
    __syncthreads();
    if (w == 0) {
        m = (l < 8) ? sm[l] : -1e30f;
        #pragma unroll
        for (int o = 4; o; o >>= 1) m = fmaxf(m, __shfl_xor_sync(0xffffffffu, m, o));
        if (l == 0) sm[0] = m;
    }
    __syncthreads();
    m = sm[0];
    float sum = 0.f;
    #pragma unroll
    for (int i = 0; i < 12; i++) {
        v[i] = __expf(v[i] - m);
        sum += v[i];
    }
    __syncthreads();
    #pragma unroll
    for (int o = 16; o; o >>= 1) sum += __shfl_xor_sync(0xffffffffu, sum, o);
    if (l == 0) sm[w] = sum;
    __syncthreads();
    if (w == 0) {
        sum = (l < 8) ? sm[l] : 0.f;
        #pragma unroll
        for (int o = 4; o; o >>= 1) sum += __shfl_xor_sync(0xffffffffu, sum, o);
        if (l == 0) sm[0] = sum;
    }
    __syncthreads();
    float inv = 1.0f / sm[0];
    #pragma unroll
    for (int i = 0; i < 12; i++) pr[t + i * 256] = v[i] * inv;
}

// ---------------- launcher ----------------
extern "C" void kernel_launch(void* const* d_in, const int* in_sizes, int n_in,
                              void* d_out, int out_size) {
    const float* x      = (const float*)d_in[0];
    const int*   offs   = (const int*)d_in[1];
    const float* fc     = (const float*)d_in[2];
    const float* ln0_g  = (const float*)d_in[3];
    const float* ln0_b  = (const float*)d_in[4];
    const float* wqkv_w = (const float*)d_in[5];
    const float* wqkv_b = (const float*)d_in[6];
    const float* wo_w   = (const float*)d_in[7];
    const float* wo_b   = (const float*)d_in[8];
    const float* ln1_g  = (const float*)d_in[9];
    const float* ln1_b  = (const float*)d_in[10];
    const float* w1     = (const float*)d_in[11];
    const float* b1     = (const float*)d_in[12];
    const float* w2     = (const float*)d_in[13];
    const float* b2     = (const float*)d_in[14];
    float* out = (float*)d_out;

    float *h, *qkv, *att, *y1, *mlp, *scores;
    int* seg;
    cudaGetSymbolAddress((void**)&h, g_h);
    cudaGetSymbolAddress((void**)&qkv, g_qkv);
    cudaGetSymbolAddress((void**)&att, g_attnout);
    cudaGetSymbolAddress((void**)&y1, g_y1);
    cudaGetSymbolAddress((void**)&mlp, g_mlp);
    cudaGetSymbolAddress((void**)&scores, g_scores);
    cudaGetSymbolAddress((void**)&seg, g_seg);

    cudaFuncSetAttribute(gemm_mma<false, 0>, cudaFuncAttributeMaxDynamicSharedMemorySize, GM_SMEM);
    cudaFuncSetAttribute(gemm_mma<false, 1>, cudaFuncAttributeMaxDynamicSharedMemorySize, GM_SMEM);
    cudaFuncSetAttribute(gemm_mma<false, 3>, cudaFuncAttributeMaxDynamicSharedMemorySize, GM_SMEM);
    cudaFuncSetAttribute(gemm_mma<true, 2>,  cudaFuncAttributeMaxDynamicSharedMemorySize, GM_SMEM);

    const float alpha = 0.11785113019775793f; // 1/sqrt(72)
    int n_off = in_sizes[1];

    // 1. LN0
    ln_kernel<<<SQ, 256>>>(x, ln0_g, ln0_b, h);

    // 2. segment ids
    seg_kernel<<<(SQ + 255) / 256, 256>>>(offs, n_off, seg);

    // 3. QKV = h @ wqkv_w + b  (3072 x 3456, K=1152)
    gemm_mma<false, 0><<<dim3(T3 / 128, SQ / 128, 1), 256, GM_SMEM>>>(
        T3, HIDD, h, HIDD, 0, wqkv_w, T3, 0, qkv, T3, 0,
        wqkv_b, nullptr, 0, nullptr, 0.f);

    // 4. RoPE on q,k
    {
        int total = SQ * NHD * (HDIM / 2);
        rope_kernel<<<(total + 255) / 256, 256>>>(qkv, fc);
    }

    // 5. scores[h] = alpha * Q K^T + segbias  (per head 3072x3072, K=72)
    gemm_mma<true, 2><<<dim3(SQ / 128, SQ / 128, NHD), 256, GM_SMEM>>>(
        SQ, HDIM,
        qkv, T3, (long)HDIM,
        qkv + HIDD, T3, (long)HDIM,
        scores, SQ, (long)SQ * SQ,
        nullptr, nullptr, 0, seg, alpha);

    // 6. softmax rows
    softmax_kernel<<<NHD * SQ, 256>>>(scores);

    // 7. attn_out[h] = P V  (3072x72, K=3072)
    gemm_mma<false, 0><<<dim3(1, SQ / 128, NHD), 256, GM_SMEM>>>(
        HDIM, SQ,
        scores, SQ, (long)SQ * SQ,
        qkv + 2 * HIDD, T3, (long)HDIM,
        att, HIDD, (long)HDIM,
        nullptr, nullptr, 0, nullptr, 0.f);

    // 8. y1 = x + attn_out @ wo_w + wo_b
    gemm_mma<false, 3><<<dim3(HIDD / 128, SQ / 128, 1), 256, GM_SMEM>>>(
        HIDD, HIDD, att, HIDD, 0, wo_w, HIDD, 0, y1, HIDD, 0,
        wo_b, x, HIDD, nullptr, 0.f);

    // 9. LN1
    ln_kernel<<<SQ, 256>>>(y1, ln1_g, ln1_b, h);

    // 10. mlp = gelu(h @ w1 + b1)  (3072 x 4304, K=1152)
    gemm_mma<false, 1><<<dim3((MLPD + 127) / 128, SQ / 128, 1), 256, GM_SMEM>>>(
        MLPD, HIDD, h, HIDD, 0, w1, MLPD, 0, mlp, MLPD, 0,
        b1, nullptr, 0, nullptr, 0.f);

    // 11. out = y1 + mlp @ w2 + b2  (3072 x 1152, K=4304)
    gemm_mma<false, 3><<<dim3(HIDD / 128, SQ / 128, 1), 256, GM_SMEM>>>(
        HIDD, MLPD, mlp, MLPD, 0, w2, HIDD, 0, out, HIDD, 0,
        b2, y1, HIDD, nullptr, 0.f);
}

// round 8
// speedup vs baseline: 2.4461x; 1.3236x over previous
#include <cuda_runtime.h>
#include <cuda_bf16.h>
#include <math.h>
#include <stdint.h>

#define SQ   3072
#define HIDD 1152
#define NHD  16
#define HDIM 72
#define MLPD 4304
#define T3   3456
#define EPSLN 1e-5f

// ---------------- scratch (allocation-free: __device__ globals) ----------------
__device__ float g_h[SQ * HIDD];
__device__ float g_qkv[SQ * T3];
__device__ float g_attnout[SQ * HIDD];
__device__ float g_y1[SQ * HIDD];
__device__ float g_mlp[(size_t)SQ * MLPD];
__device__ int   g_seg[SQ];

// ---------------- helpers ----------------
__device__ __forceinline__ uint32_t smem_u32(const void* p) {
    uint32_t a;
    asm("{ .reg .u64 t; cvta.to.shared.u64 t, %1; cvt.u32.u64 %0, t; }" : "=r"(a) : "l"(p));
    return a;
}

__device__ __forceinline__ void ldsm4(uint32_t r[4], uint32_t a) {
    asm volatile("ldmatrix.sync.aligned.m8n8.x4.shared.b16 {%0,%1,%2,%3}, [%4];"
                 : "=r"(r[0]), "=r"(r[1]), "=r"(r[2]), "=r"(r[3]) : "r"(a));
}
__device__ __forceinline__ void ldsm4t(uint32_t r[4], uint32_t a) {
    asm volatile("ldmatrix.sync.aligned.m8n8.x4.trans.shared.b16 {%0,%1,%2,%3}, [%4];"
                 : "=r"(r[0]), "=r"(r[1]), "=r"(r[2]), "=r"(r[3]) : "r"(a));
}

__device__ __forceinline__ void mma16816(float d[4], const uint32_t a[4], const uint32_t b[2]) {
    asm volatile(
        "mma.sync.aligned.m16n8k16.row.col.f32.bf16.bf16.f32 "
        "{%0,%1,%2,%3}, {%4,%5,%6,%7}, {%8,%9}, {%0,%1,%2,%3};"
        : "+f"(d[0]), "+f"(d[1]), "+f"(d[2]), "+f"(d[3])
        : "r"(a[0]), "r"(a[1]), "r"(a[2]), "r"(a[3]), "r"(b[0]), "r"(b[1]));
}

__device__ __forceinline__ void split_bf(float f, unsigned short& h, unsigned short& l) {
    __nv_bfloat16 hb = __float2bfloat16(f);
    float r = f - __bfloat162float(hb);
    __nv_bfloat16 lb = __float2bfloat16(r);
    h = __bfloat16_as_ushort(hb);
    l = __bfloat16_as_ushort(lb);
}

__device__ __forceinline__ void packsplit(float a, float b, uint32_t& hi, uint32_t& lo) {
    unsigned short ha, la, hb, lb;
    split_bf(a, ha, la);
    split_bf(b, hb, lb);
    hi = (uint32_t)ha | ((uint32_t)hb << 16);
    lo = (uint32_t)la | ((uint32_t)lb << 16);
}

__device__ __forceinline__ float gelu_tanh(float x) {
    float x3 = x * x * x;
    return 0.5f * x * (1.0f + tanhf(0.7978845608028654f * (x + 0.044715f * x3)));
}

// ================= bf16-split tensor-core GEMM (mma.sync path) =================
// MODE 0: +bias (nullable)   MODE 1: gelu(+bias)   MODE 3: +bias + resid
#define ROWB   80
#define TILEB  (128 * ROWB)
#define STAGEB (4 * TILEB)
#define GM_SMEM (2 * STAGEB)

template <int MODE>
__global__ void __launch_bounds__(256)
gemm_mma(int N, int K,
         const float* __restrict__ A, int lda,
         const float* __restrict__ B, int ldb,
         float* __restrict__ C, int ldc,
         const float* __restrict__ bias,
         const float* __restrict__ resid, int ldr) {
    extern __shared__ char smbuf[];
    const int tid = threadIdx.x;
    const int lane = tid & 31, wid = tid >> 5;
    const int wm = wid & 1, wn = wid >> 1;      // warps: 2 x 4 (m x n)
    const int m0 = blockIdx.y * 128;
    const int n0 = blockIdx.x * 128;

    const int ar  = tid >> 1;
    const int akq = (tid & 1) * 16;
    const int bn  = tid & 127;
    const int bkh = (tid >> 7) * 16;

    float4 avA[4];
    float  bvB[16];

    const int nc = (K + 31) >> 5;

    #define LDG_CHUNK(c_)  do {                                                   \
        int k0_ = (c_) * 32;                                                      \
        const float* ap_ = A + (size_t)(m0 + ar) * lda + k0_ + akq;               \
        _Pragma("unroll")                                                         \
        for (int j = 0; j < 4; j++)                                               \
            avA[j] = (k0_ + akq + 4 * j < K) ? *(const float4*)(ap_ + 4 * j)      \
                                             : make_float4(0.f, 0.f, 0.f, 0.f);   \
        bool ok_ = (n0 + bn) < N;                                                 \
        _Pragma("unroll")                                                         \
        for (int j = 0; j < 16; j++)                                              \
            bvB[j] = (ok_ && k0_ + bkh + j < K)                                   \
                         ? B[(size_t)(k0_ + bkh + j) * ldb + n0 + bn] : 0.f;      \
    } while (0)

    #define STS_CHUNK(s_)  do {                                                   \
        char* st_ = smbuf + (s_) * STAGEB;                                        \
        _Pragma("unroll")                                                         \
        for (int j = 0; j < 4; j++) {                                             \
            unsigned short h0, h1, h2, h3, l0, l1, l2, l3;                        \
            split_bf(avA[j].x, h0, l0); split_bf(avA[j].y, h1, l1);               \
            split_bf(avA[j].z, h2, l2); split_bf(avA[j].w, h3, l3);               \
            uint2 hp = make_uint2((uint32_t)h0 | ((uint32_t)h1 << 16),            \
                                  (uint32_t)h2 | ((uint32_t)h3 << 16));           \
            uint2 lp = make_uint2((uint32_t)l0 | ((uint32_t)l1 << 16),            \
                                  (uint32_t)l2 | ((uint32_t)l3 << 16));           \
            uint32_t off = (uint32_t)ar * ROWB + (uint32_t)(akq + 4 * j) * 2u;    \
            *(uint2*)(st_ + off) = hp;                                            \
            *(uint2*)(st_ + TILEB + off) = lp;                                    \
        }                                                                         \
        _Pragma("unroll")                                                         \
        for (int j = 0; j < 8; j++) {                                             \
            unsigned short h0, h1, l0, l1;                                        \
            split_bf(bvB[2 * j], h0, l0);                                         \
            split_bf(bvB[2 * j + 1], h1, l1);                                     \
            uint32_t hp = (uint32_t)h0 | ((uint32_t)h1 << 16);                    \
            uint32_t lp = (uint32_t)l0 | ((uint32_t)l1 << 16);                    \
            uint32_t off = (uint32_t)bn * ROWB + (uint32_t)(bkh + 2 * j) * 2u;    \
            *(uint32_t*)(st_ + 2 * TILEB + off) = hp;                             \
            *(uint32_t*)(st_ + 3 * TILEB + off) = lp;                             \
        }                                                                         \
    } while (0)

    float acc[4][4][4];
    #pragma unroll
    for (int mi = 0; mi < 4; mi++)
        #pragma unroll
        for (int ni = 0; ni < 4; ni++)
            #pragma unroll
            for (int e = 0; e < 4; e++) acc[mi][ni][e] = 0.f;

    const uint32_t sbase = smem_u32(smbuf);
    const uint32_t aoff = (uint32_t)(wm * 64 + (lane & 15)) * ROWB + (lane >> 4) * 16;
    const uint32_t boff = (uint32_t)(wn * 32 + ((lane >> 4) << 3) + (lane & 7)) * ROWB
                          + ((lane >> 3) & 1) * 16;

    LDG_CHUNK(0);
    STS_CHUNK(0);

    for (int c = 0; c < nc; c++) {
        __syncthreads();
        if (c + 1 < nc) LDG_CHUNK(c + 1);

        const uint32_t stb = sbase + (uint32_t)(c & 1) * STAGEB;
        #pragma unroll
        for (int kk = 0; kk < 2; kk++) {
            uint32_t ah[4][4], al[4][4], bh[4][2], bl[4][2];
            #pragma unroll
            for (int mi = 0; mi < 4; mi++) {
                uint32_t base = stb + aoff + mi * 16 * ROWB + kk * 32;
                ldsm4(ah[mi], base);
                ldsm4(al[mi], base + TILEB);
            }
            #pragma unroll
            for (int nj = 0; nj < 2; nj++) {
                uint32_t t[4];
                uint32_t base = stb + 2 * TILEB + boff + nj * 16 * ROWB + kk * 32;
                ldsm4(t, base);
                bh[2 * nj][0] = t[0]; bh[2 * nj][1] = t[1];
                bh[2 * nj + 1][0] = t[2]; bh[2 * nj + 1][1] = t[3];
                ldsm4(t, base + TILEB);
                bl[2 * nj][0] = t[0]; bl[2 * nj][1] = t[1];
                bl[2 * nj + 1][0] = t[2]; bl[2 * nj + 1][1] = t[3];
            }
            #pragma unroll
            for (int mi = 0; mi < 4; mi++)
                #pragma unroll
                for (int ni = 0; ni < 4; ni++)
                    mma16816(acc[mi][ni], ah[mi], bh[ni]);
            #pragma unroll
            for (int mi = 0; mi < 4; mi++)
                #pragma unroll
                for (int ni = 0; ni < 4; ni++)
                    mma16816(acc[mi][ni], ah[mi], bl[ni]);
            #pragma unroll
            for (int mi = 0; mi < 4; mi++)
                #pragma unroll
                for (int ni = 0; ni < 4; ni++)
                    mma16816(acc[mi][ni], al[mi], bh[ni]);
        }
        if (c + 1 < nc) STS_CHUNK((c + 1) & 1);
    }

    const int tr = lane >> 2;
    const int tc2 = (lane & 3) * 2;
    #pragma unroll
    for (int mi = 0; mi < 4; mi++) {
        #pragma unroll
        for (int h = 0; h < 2; h++) {
            int row = m0 + wm * 64 + mi * 16 + h * 8 + tr;
            float* crow = C + (size_t)row * ldc;
            const float* rrow = (MODE == 3) ? resid + (size_t)row * ldr : nullptr;
            #pragma unroll
            for (int ni = 0; ni < 4; ni++) {
                int col = n0 + wn * 32 + ni * 8 + tc2;
                if (col < N) {
                    float v0 = acc[mi][ni][2 * h];
                    float v1 = acc[mi][ni][2 * h + 1];
                    if (MODE == 0) {
                        if (bias) { v0 += bias[col]; v1 += bias[col + 1]; }
                    } else if (MODE == 1) {
                        v0 = gelu_tanh(v0 + bias[col]);
                        v1 = gelu_tanh(v1 + bias[col + 1]);
                    } else if (MODE == 3) {
                        v0 += bias[col] + rrow[col];
                        v1 += bias[col + 1] + rrow[col + 1];
                    }
                    *(float2*)(crow + col) = make_float2(v0, v1);
                }
            }
        }
    }
    #undef LDG_CHUNK
    #undef STS_CHUNK
}

// ================= fused flash attention =================
// grid (SQ/128, NHD), 256 threads (8 warps x 16 query rows).
// K padded 72->80 (5 k16 chunks); smem: Kh,Kl,Vh,Vl tiles 128x176B + seg[128].
#define VSTR   176
#define FTILE  (128 * VSTR)
#define FA_SMEM (4 * FTILE + 512)
#define ALPHA_ATT 0.11785113019775793f

__global__ void __launch_bounds__(256)
flash_attn(const float* __restrict__ qkv,
           const int* __restrict__ seg,
           float* __restrict__ out) {
    extern __shared__ char smf[];
    const int tid = threadIdx.x, lane = tid & 31, wid = tid >> 5;
    const int m0 = blockIdx.x * 128;
    const int hh = blockIdx.y;
    const int qcol = hh * HDIM;
    const uint32_t sb = smem_u32(smf);
    int* segk = (int*)(smf + 4 * FTILE);

    const int str = tid >> 1;          // staging row 0..127
    const int sth = tid & 1;           // staging half
    const int cbase = sth * 36;

    // ---- stage Q into buffers 0/1, zero all pads ----
    {
        const float* qp = qkv + (size_t)(m0 + str) * T3 + qcol + cbase;
        char* dh = smf + (size_t)str * VSTR + cbase * 2;
        char* dl = dh + FTILE;
        #pragma unroll
        for (int j = 0; j < 9; j++) {
            float4 v = *(const float4*)(qp + 4 * j);
            unsigned short h0, h1, h2, h3, l0, l1, l2, l3;
            split_bf(v.x, h0, l0); split_bf(v.y, h1, l1);
            split_bf(v.z, h2, l2); split_bf(v.w, h3, l3);
            *(uint2*)(dh + 8 * j) = make_uint2((uint32_t)h0 | ((uint32_t)h1 << 16),
                                               (uint32_t)h2 | ((uint32_t)h3 << 16));
            *(uint2*)(dl + 8 * j) = make_uint2((uint32_t)l0 | ((uint32_t)l1 << 16),
                                               (uint32_t)l2 | ((uint32_t)l3 << 16));
        }
        if (sth) {
            uint4 z = make_uint4(0, 0, 0, 0);
            #pragma unroll
            for (int t = 0; t < 4; t++)
                *(uint4*)(smf + (size_t)t * FTILE + (size_t)str * VSTR + 144) = z;
        }
    }
    __syncthreads();

    // ---- Q fragments (held in registers for the whole kernel) ----
    uint32_t qh[5][4], ql[5][4];
    {
        uint32_t qa = sb + (uint32_t)(wid * 16 + (lane & 15)) * VSTR + (lane >> 4) * 16;
        #pragma unroll
        for (int kc = 0; kc < 5; kc++) {
            ldsm4(qh[kc], qa + kc * 32);
            ldsm4(ql[kc], qa + kc * 32 + FTILE);
        }
    }

    const int tr = lane >> 2, tc = lane & 3;
    const int segq0 = seg[m0 + wid * 16 + tr];
    const int segq1 = seg[m0 + wid * 16 + tr + 8];

    float mr0 = -1e30f, mr1 = -1e30f;
    float el0 = 0.f, el1 = 0.f;
    float o[9][4];
    #pragma unroll
    for (int f = 0; f < 9; f++)
        #pragma unroll
        for (int e = 0; e < 4; e++) o[f][e] = 0.f;

    for (int kt = 0; kt < SQ / 128; kt++) {
        const int n0 = kt * 128;
        __syncthreads();
        // ---- load + convert K,V tiles ----
        {
            const float* kp = qkv + (size_t)(n0 + str) * T3 + HIDD + qcol + cbase;
            const float* vp = kp + HIDD;
            char* dkh = smf + (size_t)str * VSTR + cbase * 2;
            #pragma unroll
            for (int j = 0; j < 9; j++) {
                float4 v = *(const float4*)(kp + 4 * j);
                unsigned short h0, h1, h2, h3, l0, l1, l2, l3;
                split_bf(v.x, h0, l0); split_bf(v.y, h1, l1);
                split_bf(v.z, h2, l2); split_bf(v.w, h3, l3);
                *(uint2*)(dkh + 8 * j) = make_uint2((uint32_t)h0 | ((uint32_t)h1 << 16),
                                                    (uint32_t)h2 | ((uint32_t)h3 << 16));
                *(uint2*)(dkh + FTILE + 8 * j) = make_uint2((uint32_t)l0 | ((uint32_t)l1 << 16),
                                                            (uint32_t)l2 | ((uint32_t)l3 << 16));
            }
            #pragma unroll
            for (int j = 0; j < 9; j++) {
                float4 v = *(const float4*)(vp + 4 * j);
                unsigned short h0, h1, h2, h3, l0, l1, l2, l3;
                split_bf(v.x, h0, l0); split_bf(v.y, h1, l1);
                split_bf(v.z, h2, l2); split_bf(v.w, h3, l3);
                *(uint2*)(dkh + 2 * FTILE + 8 * j) = make_uint2((uint32_t)h0 | ((uint32_t)h1 << 16),
                                                                (uint32_t)h2 | ((uint32_t)h3 << 16));
                *(uint2*)(dkh + 3 * FTILE + 8 * j) = make_uint2((uint32_t)l0 | ((uint32_t)l1 << 16),
                                                                (uint32_t)l2 | ((uint32_t)l3 << 16));
            }
            if (tid < 128) segk[tid] = seg[n0 + tid];
        }
        __syncthreads();

        // ---- S = Q K^T (3-term bf16 split) ----
        float s[16][4];
        #pragma unroll
        for (int ni = 0; ni < 16; ni++)
            #pragma unroll
            for (int e = 0; e < 4; e++) s[ni][e] = 0.f;

        #pragma unroll
        for (int kc = 0; kc < 5; kc++) {
            #pragma unroll
            for (int nj = 0; nj < 8; nj++) {
                uint32_t bh4[4], bl4[4];
                uint32_t kb = sb + (uint32_t)(nj * 16 + ((lane >> 4) << 3) + (lane & 7)) * VSTR
                              + ((lane >> 3) & 1) * 16 + kc * 32;
                ldsm4(bh4, kb);
                ldsm4(bl4, kb + FTILE);
                mma16816(s[2 * nj],     qh[kc], bh4);
                mma16816(s[2 * nj],     qh[kc], bl4);
                mma16816(s[2 * nj],     ql[kc], bh4);
                mma16816(s[2 * nj + 1], qh[kc], bh4 + 2);
                mma16816(s[2 * nj + 1], qh[kc], bl4 + 2);
                mma16816(s[2 * nj + 1], ql[kc], bh4 + 2);
            }
        }

        // ---- alpha scale + segment bias + online softmax ----
        float rm0 = -1e30f, rm1 = -1e30f;
        #pragma unroll
        for (int ni = 0; ni < 16; ni++) {
            int sk0 = segk[ni * 8 + 2 * tc];
            int sk1 = segk[ni * 8 + 2 * tc + 1];
            s[ni][0] = fmaf(s[ni][0], ALPHA_ATT, (segq0 == sk0) ? 1.f : 0.f);
            s[ni][1] = fmaf(s[ni][1], ALPHA_ATT, (segq0 == sk1) ? 1.f : 0.f);
            s[ni][2] = fmaf(s[ni][2], ALPHA_ATT, (segq1 == sk0) ? 1.f : 0.f);
            s[ni][3] = fmaf(s[ni][3], ALPHA_ATT, (segq1 == sk1) ? 1.f : 0.f);
            rm0 = fmaxf(rm0, fmaxf(s[ni][0], s[ni][1]));
            rm1 = fmaxf(rm1, fmaxf(s[ni][2], s[ni][3]));
        }
        rm0 = fmaxf(rm0, __shfl_xor_sync(0xffffffffu, rm0, 1));
        rm0 = fmaxf(rm0, __shfl_xor_sync(0xffffffffu, rm0, 2));
        rm1 = fmaxf(rm1, __shfl_xor_sync(0xffffffffu, rm1, 1));
        rm1 = fmaxf(rm1, __shfl_xor_sync(0xffffffffu, rm1, 2));
        float mn0 = fmaxf(mr0, rm0), mn1 = fmaxf(mr1, rm1);
        float sc0 = __expf(mr0 - mn0), sc1 = __expf(mr1 - mn1);
        mr0 = mn0; mr1 = mn1;
        float rs0 = 0.f, rs1 = 0.f;
        #pragma unroll
        for (int ni = 0; ni < 16; ni++) {
            s[ni][0] = __expf(s[ni][0] - mn0); rs0 += s[ni][0];
            s[ni][1] = __expf(s[ni][1] - mn0); rs0 += s[ni][1];
            s[ni][2] = __expf(s[ni][2] - mn1); rs1 += s[ni][2];
            s[ni][3] = __expf(s[ni][3] - mn1); rs1 += s[ni][3];
        }
        rs0 += __shfl_xor_sync(0xffffffffu, rs0, 1);
        rs0 += __shfl_xor_sync(0xffffffffu, rs0, 2);
        rs1 += __shfl_xor_sync(0xffffffffu, rs1, 1);
        rs1 += __shfl_xor_sync(0xffffffffu, rs1, 2);
        el0 = el0 * sc0 + rs0;
        el1 = el1 * sc1 + rs1;
        #pragma unroll
        for (int f = 0; f < 9; f++) {
            o[f][0] *= sc0; o[f][1] *= sc0;
            o[f][2] *= sc1; o[f][3] *= sc1;
        }

        // ---- O += P V (P split hi/lo, V split hi/lo; 3 terms) ----
        #pragma unroll
        for (int kc2 = 0; kc2 < 8; kc2++) {
            uint32_t ph[4], pl[4];
            packsplit(s[2 * kc2][0],     s[2 * kc2][1],     ph[0], pl[0]);
            packsplit(s[2 * kc2][2],     s[2 * kc2][3],     ph[1], pl[1]);
            packsplit(s[2 * kc2 + 1][0], s[2 * kc2 + 1][1], ph[2], pl[2]);
            packsplit(s[2 * kc2 + 1][2], s[2 * kc2 + 1][3], ph[3], pl[3]);
            #pragma unroll
            for (int vj = 0; vj < 5; vj++) {
                uint32_t vh4[4], vl4[4];
                uint32_t va = sb + 2 * FTILE
                              + (uint32_t)(kc2 * 16 + (lane & 15)) * VSTR
                              + (uint32_t)(vj * 16 + (lane >> 4) * 8) * 2;
                ldsm4t(vh4, va);
                ldsm4t(vl4, va + FTILE);
                mma16816(o[2 * vj], ph, vh4);
                mma16816(o[2 * vj], ph, vl4);
                mma16816(o[2 * vj], pl, vh4);
                if (vj < 4) {
                    mma16816(o[2 * vj + 1], ph, vh4 + 2);
                    mma16816(o[2 * vj + 1], ph, vl4 + 2);
                    mma16816(o[2 * vj + 1], pl, vh4 + 2);
                }
            }
        }
    }

    // ---- normalize and store ----
    float i0 = 1.f / el0, i1 = 1.f / el1;
    int row0 = m0 + wid * 16 + tr;
    float* op0 = out + (size_t)row0 * HIDD + qcol;
    float* op1 = op0 + 8 * HIDD;
    #pragma unroll
    for (int f = 0; f < 9; f++) {
        int col = f * 8 + 2 * tc;
        *(float2*)(op0 + col) = make_float2(o[f][0] * i0, o[f][1] * i0);
        *(float2*)(op1 + col) = make_float2(o[f][2] * i1, o[f][3] * i1);
    }
}

// ---------------- layernorm ----------------
__global__ void ln_kernel(const float* __restrict__ x,
                          const float* __restrict__ g,
                          const float* __restrict__ b,
                          float* __restrict__ out) {
    int row = blockIdx.x;
    const float* xr = x + (size_t)row * HIDD;
    float s1 = 0.f, s2 = 0.f;
    for (int i = threadIdx.x; i < HIDD; i += blockDim.x) {
        float v = xr[i];
        s1 += v; s2 += v * v;
    }
    __shared__ float sh1[8], sh2[8];
    #pragma unroll
    for (int o = 16; o; o >>= 1) {
        s1 += __shfl_xor_sync(0xffffffffu, s1, o);
        s2 += __shfl_xor_sync(0xffffffffu, s2, o);
    }
    int w = threadIdx.x >> 5, l = threadIdx.x & 31;
    if (l == 0) { sh1[w] = s1; sh2[w] = s2; }
    __syncthreads();
    if (w == 0) {
        s1 = (l < 8) ? sh1[l] : 0.f;
        s2 = (l < 8) ? sh2[l] : 0.f;
        #pragma unroll
        for (int o = 4; o; o >>= 1) {
            s1 += __shfl_xor_sync(0xffffffffu, s1, o);
            s2 += __shfl_xor_sync(0xffffffffu, s2, o);
        }
        if (l == 0) { sh1[0] = s1; sh2[0] = s2; }
    }
    __syncthreads();
    float mu = sh1[0] * (1.0f / HIDD);
    float var = sh2[0] * (1.0f / HIDD) - mu * mu;
    float rs = rsqrtf(var + EPSLN);
    float* orow = out + (size_t)row * HIDD;
    for (int i = threadIdx.x; i < HIDD; i += blockDim.x) {
        orow[i] = (xr[i] - mu) * rs * g[i] + b[i];
    }
}

// ---------------- segment ids ----------------
__global__ void seg_kernel(const int* __restrict__ off, int n, int* __restrict__ seg) {
    int t = blockIdx.x * blockDim.x + threadIdx.x;
    if (t >= SQ) return;
    int s = 0;
    for (int i = 1; i < n; i++)
        if (t >= off[i]) s = i;
    seg[t] = s;
}

// ---------------- RoPE on q and k (in-place in qkv) ----------------
__global__ void rope_kernel(float* __restrict__ qkv, const float* __restrict__ fc) {
    int idx = blockIdx.x * blockDim.x + threadIdx.x;
    const int NP = HDIM / 2;
    if (idx >= SQ * NHD * NP) return;
    int p = idx % NP;
    int h = (idx / NP) % NHD;
    int s = idx / (NP * NHD);
    float c  = fc[s * HDIM + 2 * p];
    float sn = fc[s * HDIM + 2 * p + 1];
    size_t base = (size_t)s * T3 + h * HDIM + 2 * p;
    float a = qkv[base], b = qkv[base + 1];
    qkv[base]     = a * c - b * sn;
    qkv[base + 1] = a * sn + b * c;
    base += HIDD;
    a = qkv[base]; b = qkv[base + 1];
    qkv[base]     = a * c - b * sn;
    qkv[base + 1] = a * sn + b * c;
}

// ---------------- launcher ----------------
extern "C" void kernel_launch(void* const* d_in, const int* in_sizes, int n_in,
                              void* d_out, int out_size) {
    const float* x      = (const float*)d_in[0];
    const int*   offs   = (const int*)d_in[1];
    const float* fc     = (const float*)d_in[2];
    const float* ln0_g  = (const float*)d_in[3];
    const float* ln0_b  = (const float*)d_in[4];
    const float* wqkv_w = (const float*)d_in[5];
    const float* wqkv_b = (const float*)d_in[6];
    const float* wo_w   = (const float*)d_in[7];
    const float* wo_b   = (const float*)d_in[8];
    const float* ln1_g  = (const float*)d_in[9];
    const float* ln1_b  = (const float*)d_in[10];
    const float* w1     = (const float*)d_in[11];
    const float* b1     = (const float*)d_in[12];
    const float* w2     = (const float*)d_in[13];
    const float* b2     = (const float*)d_in[14];
    float* out = (float*)d_out;

    float *h, *qkv, *att, *y1, *mlp;
    int* seg;
    cudaGetSymbolAddress((void**)&h, g_h);
    cudaGetSymbolAddress((void**)&qkv, g_qkv);
    cudaGetSymbolAddress((void**)&att, g_attnout);
    cudaGetSymbolAddress((void**)&y1, g_y1);
    cudaGetSymbolAddress((void**)&mlp, g_mlp);
    cudaGetSymbolAddress((void**)&seg, g_seg);

    cudaFuncSetAttribute(gemm_mma<0>, cudaFuncAttributeMaxDynamicSharedMemorySize, GM_SMEM);
    cudaFuncSetAttribute(gemm_mma<1>, cudaFuncAttributeMaxDynamicSharedMemorySize, GM_SMEM);
    cudaFuncSetAttribute(gemm_mma<3>, cudaFuncAttributeMaxDynamicSharedMemorySize, GM_SMEM);
    cudaFuncSetAttribute(flash_attn, cudaFuncAttributeMaxDynamicSharedMemorySize, FA_SMEM);

    int n_off = in_sizes[1];

    // 1. LN0
    ln_kernel<<<SQ, 256>>>(x, ln0_g, ln0_b, h);

    // 2. segment ids
    seg_kernel<<<(SQ + 255) / 256, 256>>>(offs, n_off, seg);

    // 3. QKV = h @ wqkv_w + b  (3072 x 3456, K=1152)
    gemm_mma<0><<<dim3(T3 / 128, SQ / 128), 256, GM_SMEM>>>(
        T3, HIDD, h, HIDD, wqkv_w, T3, qkv, T3, wqkv_b, nullptr, 0);

    // 4. RoPE on q,k
    {
        int total = SQ * NHD * (HDIM / 2);
        rope_kernel<<<(total + 255) / 256, 256>>>(qkv, fc);
    }

    // 5. fused attention (QK^T + segbias + softmax + PV)
    flash_attn<<<dim3(SQ / 128, NHD), 256, FA_SMEM>>>(qkv, seg, att);

    // 6. y1 = x + attn_out @ wo_w + wo_b
    gemm_mma<3><<<dim3(HIDD / 128, SQ / 128), 256, GM_SMEM>>>(
        HIDD, HIDD, att, HIDD, wo_w, HIDD, y1, HIDD, wo_b, x, HIDD);

    // 7. LN1
    ln_kernel<<<SQ, 256>>>(y1, ln1_g, ln1_b, h);

    // 8. mlp = gelu(h @ w1 + b1)  (3072 x 4304, K=1152)
    gemm_mma<1><<<dim3((MLPD + 127) / 128, SQ / 128), 256, GM_SMEM>>>(
        MLPD, HIDD, h, HIDD, w1, MLPD, mlp, MLPD, b1, nullptr, 0);

    // 9. out = y1 + mlp @ w2 + b2  (3072 x 1152, K=4304)
    gemm_mma<3><<<dim3(HIDD / 128, SQ / 128), 256, GM_SMEM>>>(
        HIDD, MLPD, mlp, MLPD, w2, HIDD, out, HIDD, b2, y1, HIDD);
}

// round 9
// speedup vs baseline: 3.6220x; 1.4807x over previous
#include <cuda_runtime.h>
#include <cuda_bf16.h>
#include <math.h>
#include <stdint.h>

#define SQ   3072
#define HIDD 1152
#define NHD  16
#define HDIM 72
#define MLPD 4304
#define MLPP 4352
#define T3   3456
#define EPSLN 1e-5f

// ---------------- scratch (allocation-free: __device__ globals, zero-init bss) ----------------
__device__ unsigned short g_hh[SQ * HIDD], g_hl[SQ * HIDD];
__device__ float g_qkv[SQ * T3];
__device__ unsigned short g_qkvh[SQ * T3], g_qkvl[SQ * T3];
__device__ unsigned short g_atth[SQ * HIDD], g_attl[SQ * HIDD];
__device__ float g_y1[SQ * HIDD];
__device__ unsigned short g_mlph[(size_t)SQ * MLPP], g_mlpl[(size_t)SQ * MLPP];
__device__ unsigned short g_wqkvt_h[(size_t)T3 * HIDD], g_wqkvt_l[(size_t)T3 * HIDD];
__device__ unsigned short g_wot_h[HIDD * HIDD], g_wot_l[HIDD * HIDD];
__device__ unsigned short g_w1t_h[(size_t)MLPP * HIDD], g_w1t_l[(size_t)MLPP * HIDD];
__device__ unsigned short g_w2t_h[(size_t)HIDD * MLPP], g_w2t_l[(size_t)HIDD * MLPP];
__device__ int g_seg[SQ];

// ---------------- helpers ----------------
__device__ __forceinline__ uint32_t smem_u32(const void* p) {
    uint32_t a;
    asm("{ .reg .u64 t; cvta.to.shared.u64 t, %1; cvt.u32.u64 %0, t; }" : "=r"(a) : "l"(p));
    return a;
}
__device__ __forceinline__ void ldsm4(uint32_t r[4], uint32_t a) {
    asm volatile("ldmatrix.sync.aligned.m8n8.x4.shared.b16 {%0,%1,%2,%3}, [%4];"
                 : "=r"(r[0]), "=r"(r[1]), "=r"(r[2]), "=r"(r[3]) : "r"(a));
}
__device__ __forceinline__ void ldsm4t(uint32_t r[4], uint32_t a) {
    asm volatile("ldmatrix.sync.aligned.m8n8.x4.trans.shared.b16 {%0,%1,%2,%3}, [%4];"
                 : "=r"(r[0]), "=r"(r[1]), "=r"(r[2]), "=r"(r[3]) : "r"(a));
}
__device__ __forceinline__ void mma16816(float d[4], const uint32_t a[4], const uint32_t b[2]) {
    asm volatile(
        "mma.sync.aligned.m16n8k16.row.col.f32.bf16.bf16.f32 "
        "{%0,%1,%2,%3}, {%4,%5,%6,%7}, {%8,%9}, {%0,%1,%2,%3};"
        : "+f"(d[0]), "+f"(d[1]), "+f"(d[2]), "+f"(d[3])
        : "r"(a[0]), "r"(a[1]), "r"(a[2]), "r"(a[3]), "r"(b[0]), "r"(b[1]));
}
__device__ __forceinline__ void cpasync16(uint32_t dst, const void* src) {
    asm volatile("cp.async.cg.shared.global [%0], [%1], 16;" :: "r"(dst), "l"(src));
}
#define CP_COMMIT() asm volatile("cp.async.commit_group;" ::: "memory")
#define CP_WAIT(n)  asm volatile("cp.async.wait_group %0;" :: "n"(n) : "memory")

__device__ __forceinline__ void split_bf(float f, unsigned short& h, unsigned short& l) {
    __nv_bfloat16 hb = __float2bfloat16(f);
    float r = f - __bfloat162float(hb);
    __nv_bfloat16 lb = __float2bfloat16(r);
    h = __bfloat16_as_ushort(hb);
    l = __bfloat16_as_ushort(lb);
}
__device__ __forceinline__ void packsplit(float a, float b, uint32_t& hi, uint32_t& lo) {
    unsigned short ha, la, hb, lb;
    split_bf(a, ha, la);
    split_bf(b, hb, lb);
    hi = (uint32_t)ha | ((uint32_t)hb << 16);
    lo = (uint32_t)la | ((uint32_t)lb << 16);
}
__device__ __forceinline__ float gelu_tanh(float x) {
    float x3 = x * x * x;
    return 0.5f * x * (1.0f + tanhf(0.7978845608028654f * (x + 0.044715f * x3)));
}

// ---------------- weight convert+transpose: W (K x N fp32) -> Th,Tl (N x Kt bf16) ----------------
__global__ void convtrans(const float* __restrict__ W, int K, int N,
                          unsigned short* __restrict__ Th, unsigned short* __restrict__ Tl, int Kt) {
    __shared__ float t[32][33];
    int k0 = blockIdx.y * 32, n0 = blockIdx.x * 32;
    int tx = threadIdx.x, ty = threadIdx.y;  // 32 x 8
    #pragma unroll
    for (int i = 0; i < 4; i++) {
        int k = k0 + ty + i * 8, n = n0 + tx;
        t[ty + i * 8][tx] = (k < K && n < N) ? W[(size_t)k * N + n] : 0.f;
    }
    __syncthreads();
    #pragma unroll
    for (int i = 0; i < 4; i++) {
        int n = n0 + ty + i * 8, k = k0 + tx;
        if (n < N && k < K) {
            unsigned short h, l;
            split_bf(t[tx][ty + i * 8], h, l);
            Th[(size_t)n * Kt + k] = h;
            Tl[(size_t)n * Kt + k] = l;
        }
    }
}

// ================= pure-bf16 3-term split GEMM, cp.async 3-stage =================
// D[m][n] = sum_k (Ah+Al)[m][k] * (Bh+Bl)[n][k]  (dropping Al*Bl)
// Tiles 128x128, BK=64. smem: 3 stages x {Ah,Al,Bh,Bl each 16KB} = 192KB.
// MODE 0: fp32 +bias    MODE 1: bf16 hi/lo gelu(+bias)    MODE 3: fp32 +bias+resid
#define GB_SMEM (3 * 65536)

template <int MODE>
__global__ void __launch_bounds__(256, 1)
gemm_bf(int N, int Kp,
        const unsigned short* __restrict__ Ah_, const unsigned short* __restrict__ Al_,
        const unsigned short* __restrict__ Bh_, const unsigned short* __restrict__ Bl_,
        float* __restrict__ C, int ldc,
        unsigned short* __restrict__ OH, unsigned short* __restrict__ OL, int ldo,
        const float* __restrict__ bias,
        const float* __restrict__ resid, int ldr) {
    extern __shared__ char smbuf[];
    const uint32_t sb = smem_u32(smbuf);
    const int tid = threadIdx.x, lane = tid & 31, wid = tid >> 5;
    const int wm = wid & 1, wn = wid >> 1;
    const int m0 = blockIdx.y * 128, n0 = blockIdx.x * 128;
    const int nc = Kp >> 6;

    auto issue = [&](int c) {
        uint32_t stb = sb + (uint32_t)(c % 3) * 65536u;
        int k0 = c << 6;
        #pragma unroll
        for (int i = 0; i < 4; i++) {
            int idx = tid + 256 * i;
            int row = idx >> 3, col = idx & 7;
            uint32_t d = stb + (uint32_t)row * 128u + (((uint32_t)col * 16u) ^ (((uint32_t)row & 7u) << 4));
            size_t ao = (size_t)(m0 + row) * Kp + k0 + col * 8;
            size_t bo = (size_t)(n0 + row) * Kp + k0 + col * 8;
            cpasync16(d,          Ah_ + ao);
            cpasync16(d + 16384u, Al_ + ao);
            cpasync16(d + 32768u, Bh_ + bo);
            cpasync16(d + 49152u, Bl_ + bo);
        }
    };

    float acc[4][4][4];
    #pragma unroll
    for (int mi = 0; mi < 4; mi++)
        #pragma unroll
        for (int ni = 0; ni < 4; ni++)
            #pragma unroll
            for (int e = 0; e < 4; e++) acc[mi][ni][e] = 0.f;

    const uint32_t ra = (uint32_t)(wm * 64 + (lane & 15));
    const uint32_t xa = (ra & 7u) << 4;
    const uint32_t ca = (uint32_t)((lane >> 4) * 16);
    const uint32_t rb = (uint32_t)(wn * 32 + ((lane >> 4) << 3) + (lane & 7));
    const uint32_t xb = (rb & 7u) << 4;
    const uint32_t cb = (uint32_t)(((lane >> 3) & 1) * 16);

    issue(0); CP_COMMIT();
    issue(1); CP_COMMIT();

    for (int c = 0; c < nc; c++) {
        if (c == nc - 1) { CP_WAIT(0); } else { CP_WAIT(1); }
        __syncthreads();
        if (c + 2 < nc) { issue(c + 2); CP_COMMIT(); }

        const uint32_t stb = sb + (uint32_t)(c % 3) * 65536u;
        #pragma unroll
        for (int kk = 0; kk < 4; kk++) {
            uint32_t ah[4][4], al[4][4], bh[4][2], bl[4][2];
            #pragma unroll
            for (int mi = 0; mi < 4; mi++) {
                uint32_t ad = stb + (ra + mi * 16u) * 128u + ((ca + kk * 32u) ^ xa);
                ldsm4(ah[mi], ad);
                ldsm4(al[mi], ad + 16384u);
            }
            #pragma unroll
            for (int nj = 0; nj < 2; nj++) {
                uint32_t t[4];
                uint32_t bd = stb + 32768u + (rb + nj * 16u) * 128u + ((cb + kk * 32u) ^ xb);
                ldsm4(t, bd);
                bh[2 * nj][0] = t[0]; bh[2 * nj][1] = t[1];
                bh[2 * nj + 1][0] = t[2]; bh[2 * nj + 1][1] = t[3];
                ldsm4(t, bd + 16384u);
                bl[2 * nj][0] = t[0]; bl[2 * nj][1] = t[1];
                bl[2 * nj + 1][0] = t[2]; bl[2 * nj + 1][1] = t[3];
            }
            #pragma unroll
            for (int mi = 0; mi < 4; mi++)
                #pragma unroll
                for (int ni = 0; ni < 4; ni++)
                    mma16816(acc[mi][ni], ah[mi], bh[ni]);
            #pragma unroll
            for (int mi = 0; mi < 4; mi++)
                #pragma unroll
                for (int ni = 0; ni < 4; ni++)
                    mma16816(acc[mi][ni], ah[mi], bl[ni]);
            #pragma unroll
            for (int mi = 0; mi < 4; mi++)
                #pragma unroll
                for (int ni = 0; ni < 4; ni++)
                    mma16816(acc[mi][ni], al[mi], bh[ni]);
        }
    }

    // ---- epilogue ----
    const int tr = lane >> 2;
    const int tc2 = (lane & 3) * 2;
    #pragma unroll
    for (int mi = 0; mi < 4; mi++) {
        #pragma unroll
        for (int h2 = 0; h2 < 2; h2++) {
            int row = m0 + wm * 64 + mi * 16 + h2 * 8 + tr;
            float* crow = (MODE != 1) ? C + (size_t)row * ldc : nullptr;
            const float* rrow = (MODE == 3) ? resid + (size_t)row * ldr : nullptr;
            #pragma unroll
            for (int ni = 0; ni < 4; ni++) {
                int col = n0 + wn * 32 + ni * 8 + tc2;
                if (col < N) {
                    float v0 = acc[mi][ni][2 * h2];
                    float v1 = acc[mi][ni][2 * h2 + 1];
                    if (MODE == 0) {
                        v0 += bias[col]; v1 += bias[col + 1];
                        *(float2*)(crow + col) = make_float2(v0, v1);
                    } else if (MODE == 1) {
                        v0 = gelu_tanh(v0 + bias[col]);
                        v1 = gelu_tanh(v1 + bias[col + 1]);
                        uint32_t hp, lp;
                        packsplit(v0, v1, hp, lp);
                        *(uint32_t*)(OH + (size_t)row * ldo + col) = hp;
                        *(uint32_t*)(OL + (size_t)row * ldo + col) = lp;
                    } else {
                        v0 += bias[col] + rrow[col];
                        v1 += bias[col + 1] + rrow[col + 1];
                        *(float2*)(crow + col) = make_float2(v0, v1);
                    }
                }
            }
        }
    }
}

// ================= fused flash attention (bf16 hi/lo pre-split inputs) =================
#define VSTR   176
#define FTILE  (128 * VSTR)
#define FA_SMEM (4 * FTILE + 512)
#define ALPHA_ATT 0.11785113019775793f

__global__ void __launch_bounds__(256, 1)
flash_attn(const unsigned short* __restrict__ qkvh,
           const unsigned short* __restrict__ qkvl,
           const int* __restrict__ seg,
           unsigned short* __restrict__ atth,
           unsigned short* __restrict__ attl) {
    extern __shared__ char smf[];
    const int tid = threadIdx.x, lane = tid & 31, wid = tid >> 5;
    const int m0 = blockIdx.x * 128;
    const int hh = blockIdx.y;
    const int qcol = hh * HDIM;
    const uint32_t sb = smem_u32(smf);
    int* segk = (int*)(smf + 4 * FTILE);

    // ---- zero pad columns (bytes 144..159 of each row, all 4 tiles) ----
    {
        uint4 z = make_uint4(0, 0, 0, 0);
        #pragma unroll
        for (int i = 0; i < 2; i++) {
            int idx = tid + 256 * i;
            int tile = idx >> 7, r = idx & 127;
            *(uint4*)(smf + (size_t)tile * FTILE + (size_t)r * VSTR + 144) = z;
        }
    }

    // ---- stage Q (hi->tile0, lo->tile1) via cp.async ----
    {
        #pragma unroll
        for (int i = 0; i < 9; i++) {
            int idx = tid + 256 * i;           // 0..2303
            int tile = idx / 1152;
            int rem = idx - tile * 1152;
            int r = rem / 9, cc = rem - r * 9;
            const unsigned short* src = (tile ? qkvl : qkvh) + (size_t)(m0 + r) * T3 + qcol + cc * 8;
            cpasync16(sb + (uint32_t)tile * FTILE + (uint32_t)r * VSTR + cc * 16, src);
        }
        CP_COMMIT();
        CP_WAIT(0);
    }
    __syncthreads();

    // ---- Q fragments (registers, whole kernel) ----
    uint32_t qh[5][4], ql[5][4];
    {
        uint32_t qa = sb + (uint32_t)(wid * 16 + (lane & 15)) * VSTR + (lane >> 4) * 16;
        #pragma unroll
        for (int kc = 0; kc < 5; kc++) {
            ldsm4(qh[kc], qa + kc * 32);
            ldsm4(ql[kc], qa + kc * 32 + FTILE);
        }
    }

    const int tr = lane >> 2, tc = lane & 3;
    const int segq0 = seg[m0 + wid * 16 + tr];
    const int segq1 = seg[m0 + wid * 16 + tr + 8];

    float mr0 = -1e30f, mr1 = -1e30f;
    float el0 = 0.f, el1 = 0.f;
    float o[9][4];
    #pragma unroll
    for (int f = 0; f < 9; f++)
        #pragma unroll
        for (int e = 0; e < 4; e++) o[f][e] = 0.f;

    for (int kt = 0; kt < SQ / 128; kt++) {
        const int n0 = kt * 128;
        __syncthreads();
        // ---- cp.async K,V tiles (Kh,Kl,Vh,Vl) ----
        {
            const unsigned short* b0 = qkvh + (size_t)n0 * T3 + HIDD + qcol;
            const unsigned short* b1 = qkvl + (size_t)n0 * T3 + HIDD + qcol;
            const unsigned short* b2 = b0 + HIDD;
            const unsigned short* b3 = b1 + HIDD;
            #pragma unroll
            for (int i = 0; i < 18; i++) {
                int idx = tid + 256 * i;         // 0..4607
                int tile = idx / 1152;
                int rem = idx - tile * 1152;
                int r = rem / 9, cc = rem - r * 9;
                const unsigned short* src =
                    (tile == 0 ? b0 : tile == 1 ? b1 : tile == 2 ? b2 : b3)
                    + (size_t)r * T3 + cc * 8;
                cpasync16(sb + (uint32_t)tile * FTILE + (uint32_t)r * VSTR + cc * 16, src);
            }
            if (tid < 128) segk[tid] = seg[n0 + tid];
            CP_COMMIT();
            CP_WAIT(0);
        }
        __syncthreads();

        // ---- S = Q K^T (3-term) ----
        float s[16][4];
        #pragma unroll
        for (int ni = 0; ni < 16; ni++)
            #pragma unroll
            for (int e = 0; e < 4; e++) s[ni][e] = 0.f;

        #pragma unroll
        for (int kc = 0; kc < 5; kc++) {
            #pragma unroll
            for (int nj = 0; nj < 8; nj++) {
                uint32_t bh4[4], bl4[4];
                uint32_t kb = sb + (uint32_t)(nj * 16 + ((lane >> 4) << 3) + (lane & 7)) * VSTR
                              + ((lane >> 3) & 1) * 16 + kc * 32;
                ldsm4(bh4, kb);
                ldsm4(bl4, kb + FTILE);
                mma16816(s[2 * nj],     qh[kc], bh4);
                mma16816(s[2 * nj],     qh[kc], bl4);
                mma16816(s[2 * nj],     ql[kc], bh4);
                mma16816(s[2 * nj + 1], qh[kc], bh4 + 2);
                mma16816(s[2 * nj + 1], qh[kc], bl4 + 2);
                mma16816(s[2 * nj + 1], ql[kc], bh4 + 2);
            }
        }

        // ---- alpha scale + segment bias + online softmax ----
        float rm0 = -1e30f, rm1 = -1e30f;
        #pragma unroll
        for (int ni = 0; ni < 16; ni++) {
            int sk0 = segk[ni * 8 + 2 * tc];
            int sk1 = segk[ni * 8 + 2 * tc + 1];
            s[ni][0] = fmaf(s[ni][0], ALPHA_ATT, (segq0 == sk0) ? 1.f : 0.f);
            s[ni][1] = fmaf(s[ni][1], ALPHA_ATT, (segq0 == sk1) ? 1.f : 0.f);
            s[ni][2] = fmaf(s[ni][2], ALPHA_ATT, (segq1 == sk0) ? 1.f : 0.f);
            s[ni][3] = fmaf(s[ni][3], ALPHA_ATT, (segq1 == sk1) ? 1.f : 0.f);
            rm0 = fmaxf(rm0, fmaxf(s[ni][0], s[ni][1]));
            rm1 = fmaxf(rm1, fmaxf(s[ni][2], s[ni][3]));
        }
        rm0 = fmaxf(rm0, __shfl_xor_sync(0xffffffffu, rm0, 1));
        rm0 = fmaxf(rm0, __shfl_xor_sync(0xffffffffu, rm0, 2));
        rm1 = fmaxf(rm1, __shfl_xor_sync(0xffffffffu, rm1, 1));
        rm1 = fmaxf(rm1, __shfl_xor_sync(0xffffffffu, rm1, 2));
        float mn0 = fmaxf(mr0, rm0), mn1 = fmaxf(mr1, rm1);
        float sc0 = __expf(mr0 - mn0), sc1 = __expf(mr1 - mn1);
        mr0 = mn0; mr1 = mn1;
        float rs0 = 0.f, rs1 = 0.f;
        #pragma unroll
        for (int ni = 0; ni < 16; ni++) {
            s[ni][0] = __expf(s[ni][0] - mn0); rs0 += s[ni][0];
            s[ni][1] = __expf(s[ni][1] - mn0); rs0 += s[ni][1];
            s[ni][2] = __expf(s[ni][2] - mn1); rs1 += s[ni][2];
            s[ni][3] = __expf(s[ni][3] - mn1); rs1 += s[ni][3];
        }
        rs0 += __shfl_xor_sync(0xffffffffu, rs0, 1);
        rs0 += __shfl_xor_sync(0xffffffffu, rs0, 2);
        rs1 += __shfl_xor_sync(0xffffffffu, rs1, 1);
        rs1 += __shfl_xor_sync(0xffffffffu, rs1, 2);
        el0 = el0 * sc0 + rs0;
        el1 = el1 * sc1 + rs1;
        #pragma unroll
        for (int f = 0; f < 9; f++) {
            o[f][0] *= sc0; o[f][1] *= sc0;
            o[f][2] *= sc1; o[f][3] *= sc1;
        }

        // ---- O += P V (3-term) ----
        #pragma unroll
        for (int kc2 = 0; kc2 < 8; kc2++) {
            uint32_t ph[4], pl[4];
            packsplit(s[2 * kc2][0],     s[2 * kc2][1],     ph[0], pl[0]);
            packsplit(s[2 * kc2][2],     s[2 * kc2][3],     ph[1], pl[1]);
            packsplit(s[2 * kc2 + 1][0], s[2 * kc2 + 1][1], ph[2], pl[2]);
            packsplit(s[2 * kc2 + 1][2], s[2 * kc2 + 1][3], ph[3], pl[3]);
            #pragma unroll
            for (int vj = 0; vj < 5; vj++) {
                uint32_t vh4[4], vl4[4];
                uint32_t va = sb + 2 * FTILE
                              + (uint32_t)(kc2 * 16 + (lane & 15)) * VSTR
                              + (uint32_t)(vj * 16 + (lane >> 4) * 8) * 2;
                ldsm4t(vh4, va);
                ldsm4t(vl4, va + FTILE);
                mma16816(o[2 * vj], ph, vh4);
                mma16816(o[2 * vj], ph, vl4);
                mma16816(o[2 * vj], pl, vh4);
                if (vj < 4) {
                    mma16816(o[2 * vj + 1], ph, vh4 + 2);
                    mma16816(o[2 * vj + 1], ph, vl4 + 2);
                    mma16816(o[2 * vj + 1], pl, vh4 + 2);
                }
            }
        }
    }

    // ---- normalize, split, store bf16 hi/lo ----
    float i0 = 1.f / el0, i1 = 1.f / el1;
    int row0 = m0 + wid * 16 + tr;
    size_t ob0 = (size_t)row0 * HIDD + qcol;
    size_t ob1 = ob0 + (size_t)8 * HIDD;
    #pragma unroll
    for (int f = 0; f < 9; f++) {
        int col = f * 8 + 2 * tc;
        uint32_t hp, lp;
        packsplit(o[f][0] * i0, o[f][1] * i0, hp, lp);
        *(uint32_t*)(atth + ob0 + col) = hp;
        *(uint32_t*)(attl + ob0 + col) = lp;
        packsplit(o[f][2] * i1, o[f][3] * i1, hp, lp);
        *(uint32_t*)(atth + ob1 + col) = hp;
        *(uint32_t*)(attl + ob1 + col) = lp;
    }
}

// ---------------- layernorm -> bf16 hi/lo ----------------
__global__ void ln_kernel(const float* __restrict__ x,
                          const float* __restrict__ g,
                          const float* __restrict__ b,
                          unsigned short* __restrict__ oh,
                          unsigned short* __restrict__ ol) {
    int row = blockIdx.x;
    const float* xr = x + (size_t)row * HIDD;
    float s1 = 0.f, s2 = 0.f;
    for (int i = threadIdx.x; i < HIDD; i += blockDim.x) {
        float v = xr[i];
        s1 += v; s2 += v * v;
    }
    __shared__ float sh1[8], sh2[8];
    #pragma unroll
    for (int o2 = 16; o2; o2 >>= 1) {
        s1 += __shfl_xor_sync(0xffffffffu, s1, o2);
        s2 += __shfl_xor_sync(0xffffffffu, s2, o2);
    }
    int w = threadIdx.x >> 5, l = threadIdx.x & 31;
    if (l == 0) { sh1[w] = s1; sh2[w] = s2; }
    __syncthreads();
    if (w == 0) {
        s1 = (l < 8) ? sh1[l] : 0.f;
        s2 = (l < 8) ? sh2[l] : 0.f;
        #pragma unroll
        for (int o2 = 4; o2; o2 >>= 1) {
            s1 += __shfl_xor_sync(0xffffffffu, s1, o2);
            s2 += __shfl_xor_sync(0xffffffffu, s2, o2);
        }
        if (l == 0) { sh1[0] = s1; sh2[0] = s2; }
    }
    __syncthreads();
    float mu = sh1[0] * (1.0f / HIDD);
    float var = sh2[0] * (1.0f / HIDD) - mu * mu;
    float rs = rsqrtf(var + EPSLN);
    for (int i = threadIdx.x; i < HIDD; i += blockDim.x) {
        float v = (xr[i] - mu) * rs * g[i] + b[i];
        unsigned short hv, lv;
        split_bf(v, hv, lv);
        oh[(size_t)row * HIDD + i] = hv;
        ol[(size_t)row * HIDD + i] = lv;
    }
}

// ---------------- segment ids ----------------
__global__ void seg_kernel(const int* __restrict__ off, int n, int* __restrict__ seg) {
    int t = blockIdx.x * blockDim.x + threadIdx.x;
    if (t >= SQ) return;
    int s = 0;
    for (int i = 1; i < n; i++)
        if (t >= off[i]) s = i;
    seg[t] = s;
}

// ---------------- RoPE (q,k) + split-convert whole qkv to bf16 hi/lo ----------------
__global__ void rope_conv(const float* __restrict__ qkv, const float* __restrict__ fc,
                          unsigned short* __restrict__ oh, unsigned short* __restrict__ ol) {
    int idx = blockIdx.x * blockDim.x + threadIdx.x;
    if (idx >= SQ * (T3 / 2)) return;
    int s = idx / (T3 / 2);
    int col = (idx - s * (T3 / 2)) * 2;
    size_t base = (size_t)s * T3 + col;
    float a = qkv[base], b = qkv[base + 1];
    if (col < 2 * HIDD) {
        int d = (col % HIDD) % HDIM;
        float c = fc[s * HDIM + d], sn = fc[s * HDIM + d + 1];
        float ra = a * c - b * sn;
        float rb = a * sn + b * c;
        a = ra; b = rb;
    }
    uint32_t hp, lp;
    packsplit(a, b, hp, lp);
    *(uint32_t*)(oh + base) = hp;
    *(uint32_t*)(ol + base) = lp;
}

// ---------------- launcher ----------------
extern "C" void kernel_launch(void* const* d_in, const int* in_sizes, int n_in,
                              void* d_out, int out_size) {
    const float* x      = (const float*)d_in[0];
    const int*   offs   = (const int*)d_in[1];
    const float* fc     = (const float*)d_in[2];
    const float* ln0_g  = (const float*)d_in[3];
    const float* ln0_b  = (const float*)d_in[4];
    const float* wqkv_w = (const float*)d_in[5];
    const float* wqkv_b = (const float*)d_in[6];
    const float* wo_w   = (const float*)d_in[7];
    const float* wo_b   = (const float*)d_in[8];
    const float* ln1_g  = (const float*)d_in[9];
    const float* ln1_b  = (const float*)d_in[10];
    const float* w1     = (const float*)d_in[11];
    const float* b1     = (const float*)d_in[12];
    const float* w2     = (const float*)d_in[13];
    const float* b2     = (const float*)d_in[14];
    float* out = (float*)d_out;

    unsigned short *hh, *hl, *qkvh, *qkvl, *atth, *attl, *mlph, *mlpl;
    unsigned short *wqt_h, *wqt_l, *wot_h, *wot_l, *w1t_h, *w1t_l, *w2t_h, *w2t_l;
    float *qkv, *y1;
    int* seg;
    cudaGetSymbolAddress((void**)&hh, g_hh);
    cudaGetSymbolAddress((void**)&hl, g_hl);
    cudaGetSymbolAddress((void**)&qkv, g_qkv);
    cudaGetSymbolAddress((void**)&qkvh, g_qkvh);
    cudaGetSymbolAddress((void**)&qkvl, g_qkvl);
    cudaGetSymbolAddress((void**)&atth, g_atth);
    cudaGetSymbolAddress((void**)&attl, g_attl);
    cudaGetSymbolAddress((void**)&y1, g_y1);
    cudaGetSymbolAddress((void**)&mlph, g_mlph);
    cudaGetSymbolAddress((void**)&mlpl, g_mlpl);
    cudaGetSymbolAddress((void**)&wqt_h, g_wqkvt_h);
    cudaGetSymbolAddress((void**)&wqt_l, g_wqkvt_l);
    cudaGetSymbolAddress((void**)&wot_h, g_wot_h);
    cudaGetSymbolAddress((void**)&wot_l, g_wot_l);
    cudaGetSymbolAddress((void**)&w1t_h, g_w1t_h);
    cudaGetSymbolAddress((void**)&w1t_l, g_w1t_l);
    cudaGetSymbolAddress((void**)&w2t_h, g_w2t_h);
    cudaGetSymbolAddress((void**)&w2t_l, g_w2t_l);
    cudaGetSymbolAddress((void**)&seg, g_seg);

    cudaFuncSetAttribute(gemm_bf<0>, cudaFuncAttributeMaxDynamicSharedMemorySize, GB_SMEM);
    cudaFuncSetAttribute(gemm_bf<1>, cudaFuncAttributeMaxDynamicSharedMemorySize, GB_SMEM);
    cudaFuncSetAttribute(gemm_bf<3>, cudaFuncAttributeMaxDynamicSharedMemorySize, GB_SMEM);
    cudaFuncSetAttribute(flash_attn, cudaFuncAttributeMaxDynamicSharedMemorySize, FA_SMEM);

    int n_off = in_sizes[1];
    dim3 ctb(32, 8);

    // 0. weight convert+transpose (once per launch)
    convtrans<<<dim3(T3 / 32, HIDD / 32), ctb>>>(wqkv_w, HIDD, T3, wqt_h, wqt_l, HIDD);
    convtrans<<<dim3(HIDD / 32, HIDD / 32), ctb>>>(wo_w, HIDD, HIDD, wot_h, wot_l, HIDD);
    convtrans<<<dim3((MLPD + 31) / 32, HIDD / 32), ctb>>>(w1, HIDD, MLPD, w1t_h, w1t_l, HIDD);
    convtrans<<<dim3(HIDD / 32, (MLPD + 31) / 32), ctb>>>(w2, MLPD, HIDD, w2t_h, w2t_l, MLPP);

    // 1. LN0 -> h (bf16 hi/lo)
    ln_kernel<<<SQ, 256>>>(x, ln0_g, ln0_b, hh, hl);

    // 2. segment ids
    seg_kernel<<<(SQ + 255) / 256, 256>>>(offs, n_off, seg);

    // 3. QKV = h @ Wqkv + b  -> fp32
    gemm_bf<0><<<dim3(T3 / 128, SQ / 128), 256, GB_SMEM>>>(
        T3, HIDD, hh, hl, wqt_h, wqt_l, qkv, T3,
        nullptr, nullptr, 0, wqkv_b, nullptr, 0);

    // 4. RoPE + split to bf16
    {
        int total = SQ * (T3 / 2);
        rope_conv<<<(total + 255) / 256, 256>>>(qkv, fc, qkvh, qkvl);
    }

    // 5. fused attention -> att (bf16 hi/lo)
    flash_attn<<<dim3(SQ / 128, NHD), 256, FA_SMEM>>>(qkvh, qkvl, seg, atth, attl);

    // 6. y1 = x + att @ Wo + b
    gemm_bf<3><<<dim3(HIDD / 128, SQ / 128), 256, GB_SMEM>>>(
        HIDD, HIDD, atth, attl, wot_h, wot_l, y1, HIDD,
        nullptr, nullptr, 0, wo_b, x, HIDD);

    // 7. LN1 -> h (bf16 hi/lo)
    ln_kernel<<<SQ, 256>>>(y1, ln1_g, ln1_b, hh, hl);

    // 8. mlp = gelu(h @ W1 + b1) -> bf16 hi/lo (padded to 4352)
    gemm_bf<1><<<dim3(MLPP / 128, SQ / 128), 256, GB_SMEM>>>(
        MLPD, HIDD, hh, hl, w1t_h, w1t_l, nullptr, 0,
        mlph, mlpl, MLPP, b1, nullptr, 0);

    // 9. out = y1 + mlp @ W2 + b2
    gemm_bf<3><<<dim3(HIDD / 128, SQ / 128), 256, GB_SMEM>>>(
        HIDD, MLPP, mlph, mlpl, w2t_h, w2t_l, out, HIDD,
        nullptr, nullptr, 0, b2, y1, HIDD);
}

// round 10
// speedup vs baseline: 3.6549x; 1.0091x over previous
#include <cuda_runtime.h>
#include <cuda_bf16.h>
#include <math.h>
#include <stdint.h>

#define SQ   3072
#define HIDD 1152
#define NHD  16
#define HDIM 72
#define MLPD 4304
#define MLPP 4352
#define T3   3456
#define EPSLN 1e-5f

// ---------------- scratch (allocation-free: __device__ globals) ----------------
__device__ unsigned short g_hh[SQ * HIDD], g_hl[SQ * HIDD];
__device__ unsigned short g_qkvh[SQ * T3], g_qkvl[SQ * T3];
__device__ unsigned short g_atth[SQ * HIDD], g_attl[SQ * HIDD];
__device__ float g_y1[SQ * HIDD];
__device__ unsigned short g_mlph[(size_t)SQ * MLPP], g_mlpl[(size_t)SQ * MLPP];
__device__ unsigned short g_wqkvt_h[(size_t)T3 * HIDD], g_wqkvt_l[(size_t)T3 * HIDD];
__device__ unsigned short g_wot_h[HIDD * HIDD], g_wot_l[HIDD * HIDD];
__device__ unsigned short g_w1t_h[(size_t)MLPP * HIDD], g_w1t_l[(size_t)MLPP * HIDD];
__device__ unsigned short g_w2t_h[(size_t)HIDD * MLPP], g_w2t_l[(size_t)HIDD * MLPP];
__device__ int g_seg[SQ];

// ---------------- helpers ----------------
__device__ __forceinline__ uint32_t smem_u32(const void* p) {
    uint32_t a;
    asm("{ .reg .u64 t; cvta.to.shared.u64 t, %1; cvt.u32.u64 %0, t; }" : "=r"(a) : "l"(p));
    return a;
}
__device__ __forceinline__ void ldsm4(uint32_t r[4], uint32_t a) {
    asm volatile("ldmatrix.sync.aligned.m8n8.x4.shared.b16 {%0,%1,%2,%3}, [%4];"
                 : "=r"(r[0]), "=r"(r[1]), "=r"(r[2]), "=r"(r[3]) : "r"(a));
}
__device__ __forceinline__ void ldsm4t(uint32_t r[4], uint32_t a) {
    asm volatile("ldmatrix.sync.aligned.m8n8.x4.trans.shared.b16 {%0,%1,%2,%3}, [%4];"
                 : "=r"(r[0]), "=r"(r[1]), "=r"(r[2]), "=r"(r[3]) : "r"(a));
}
__device__ __forceinline__ void mma16816(float d[4], const uint32_t a[4], const uint32_t b[2]) {
    asm volatile(
        "mma.sync.aligned.m16n8k16.row.col.f32.bf16.bf16.f32 "
        "{%0,%1,%2,%3}, {%4,%5,%6,%7}, {%8,%9}, {%0,%1,%2,%3};"
        : "+f"(d[0]), "+f"(d[1]), "+f"(d[2]), "+f"(d[3])
        : "r"(a[0]), "r"(a[1]), "r"(a[2]), "r"(a[3]), "r"(b[0]), "r"(b[1]));
}
__device__ __forceinline__ void cpasync16(uint32_t dst, const void* src) {
    asm volatile("cp.async.cg.shared.global [%0], [%1], 16;" :: "r"(dst), "l"(src));
}
#define CP_COMMIT() asm volatile("cp.async.commit_group;" ::: "memory")
#define CP_WAIT(n)  asm volatile("cp.async.wait_group %0;" :: "n"(n) : "memory")

__device__ __forceinline__ void split_bf(float f, unsigned short& h, unsigned short& l) {
    __nv_bfloat16 hb = __float2bfloat16(f);
    float r = f - __bfloat162float(hb);
    __nv_bfloat16 lb = __float2bfloat16(r);
    h = __bfloat16_as_ushort(hb);
    l = __bfloat16_as_ushort(lb);
}
__device__ __forceinline__ void packsplit(float a, float b, uint32_t& hi, uint32_t& lo) {
    unsigned short ha, la, hb, lb;
    split_bf(a, ha, la);
    split_bf(b, hb, lb);
    hi = (uint32_t)ha | ((uint32_t)hb << 16);
    lo = (uint32_t)la | ((uint32_t)lb << 16);
}
__device__ __forceinline__ float gelu_tanh(float x) {
    float x3 = x * x * x;
    return 0.5f * x * (1.0f + tanhf(0.7978845608028654f * (x + 0.044715f * x3)));
}

// ---------------- weight convert+transpose: W (K x N fp32) -> Th,Tl (N x Kt bf16) ----------------
__global__ void convtrans(const float* __restrict__ W, int K, int N,
                          unsigned short* __restrict__ Th, unsigned short* __restrict__ Tl, int Kt) {
    __shared__ float t[32][33];
    int k0 = blockIdx.y * 32, n0 = blockIdx.x * 32;
    int tx = threadIdx.x, ty = threadIdx.y;  // 32 x 8
    #pragma unroll
    for (int i = 0; i < 4; i++) {
        int k = k0 + ty + i * 8, n = n0 + tx;
        t[ty + i * 8][tx] = (k < K && n < N) ? W[(size_t)k * N + n] : 0.f;
    }
    __syncthreads();
    #pragma unroll
    for (int i = 0; i < 4; i++) {
        int n = n0 + ty + i * 8, k = k0 + tx;
        if (n < N && k < K) {
            unsigned short h, l;
            split_bf(t[tx][ty + i * 8], h, l);
            Th[(size_t)n * Kt + k] = h;
            Tl[(size_t)n * Kt + k] = l;
        }
    }
}

// ================= pure-bf16 3-term split GEMM, cp.async 3-stage =================
// MODE 1: bf16 hi/lo gelu(+bias)   MODE 3: fp32 +bias+resid
// MODE 4: +bias, RoPE on cols<2*HIDD (aux = freqs_cis, row-major S x HDIM), bf16 hi/lo out
#define GB_SMEM (3 * 65536)

template <int MODE>
__global__ void __launch_bounds__(256, 1)
gemm_bf(int N, int Kp,
        const unsigned short* __restrict__ Ah_, const unsigned short* __restrict__ Al_,
        const unsigned short* __restrict__ Bh_, const unsigned short* __restrict__ Bl_,
        float* __restrict__ C, int ldc,
        unsigned short* __restrict__ OH, unsigned short* __restrict__ OL, int ldo,
        const float* __restrict__ bias,
        const float* __restrict__ aux, int ldr) {
    extern __shared__ char smbuf[];
    const uint32_t sb = smem_u32(smbuf);
    const int tid = threadIdx.x, lane = tid & 31, wid = tid >> 5;
    const int wm = wid & 1, wn = wid >> 1;
    const int m0 = blockIdx.y * 128, n0 = blockIdx.x * 128;
    const int nc = Kp >> 6;

    auto issue = [&](int c) {
        uint32_t stb = sb + (uint32_t)(c % 3) * 65536u;
        int k0 = c << 6;
        #pragma unroll
        for (int i = 0; i < 4; i++) {
            int idx = tid + 256 * i;
            int row = idx >> 3, col = idx & 7;
            uint32_t d = stb + (uint32_t)row * 128u + (((uint32_t)col * 16u) ^ (((uint32_t)row & 7u) << 4));
            size_t ao = (size_t)(m0 + row) * Kp + k0 + col * 8;
            size_t bo = (size_t)(n0 + row) * Kp + k0 + col * 8;
            cpasync16(d,          Ah_ + ao);
            cpasync16(d + 16384u, Al_ + ao);
            cpasync16(d + 32768u, Bh_ + bo);
            cpasync16(d + 49152u, Bl_ + bo);
        }
    };

    float acc[4][4][4];
    #pragma unroll
    for (int mi = 0; mi < 4; mi++)
        #pragma unroll
        for (int ni = 0; ni < 4; ni++)
            #pragma unroll
            for (int e = 0; e < 4; e++) acc[mi][ni][e] = 0.f;

    const uint32_t ra = (uint32_t)(wm * 64 + (lane & 15));
    const uint32_t xa = (ra & 7u) << 4;
    const uint32_t ca = (uint32_t)((lane >> 4) * 16);
    const uint32_t rb = (uint32_t)(wn * 32 + ((lane >> 4) << 3) + (lane & 7));
    const uint32_t xb = (rb & 7u) << 4;
    const uint32_t cb = (uint32_t)(((lane >> 3) & 1) * 16);

    issue(0); CP_COMMIT();
    issue(1); CP_COMMIT();

    for (int c = 0; c < nc; c++) {
        if (c == nc - 1) { CP_WAIT(0); } else { CP_WAIT(1); }
        __syncthreads();
        if (c + 2 < nc) { issue(c + 2); CP_COMMIT(); }

        const uint32_t stb = sb + (uint32_t)(c % 3) * 65536u;
        #pragma unroll
        for (int kk = 0; kk < 4; kk++) {
            uint32_t ah[4][4], al[4][4], bh[4][2], bl[4][2];
            #pragma unroll
            for (int mi = 0; mi < 4; mi++) {
                uint32_t ad = stb + (ra + mi * 16u) * 128u + ((ca + kk * 32u) ^ xa);
                ldsm4(ah[mi], ad);
                ldsm4(al[mi], ad + 16384u);
            }
            #pragma unroll
            for (int nj = 0; nj < 2; nj++) {
                uint32_t t[4];
                uint32_t bd = stb + 32768u + (rb + nj * 16u) * 128u + ((cb + kk * 32u) ^ xb);
                ldsm4(t, bd);
                bh[2 * nj][0] = t[0]; bh[2 * nj][1] = t[1];
                bh[2 * nj + 1][0] = t[2]; bh[2 * nj + 1][1] = t[3];
                ldsm4(t, bd + 16384u);
                bl[2 * nj][0] = t[0]; bl[2 * nj][1] = t[1];
                bl[2 * nj + 1][0] = t[2]; bl[2 * nj + 1][1] = t[3];
            }
            #pragma unroll
            for (int mi = 0; mi < 4; mi++)
                #pragma unroll
                for (int ni = 0; ni < 4; ni++)
                    mma16816(acc[mi][ni], ah[mi], bh[ni]);
            #pragma unroll
            for (int mi = 0; mi < 4; mi++)
                #pragma unroll
                for (int ni = 0; ni < 4; ni++)
                    mma16816(acc[mi][ni], ah[mi], bl[ni]);
            #pragma unroll
            for (int mi = 0; mi < 4; mi++)
                #pragma unroll
                for (int ni = 0; ni < 4; ni++)
                    mma16816(acc[mi][ni], al[mi], bh[ni]);
        }
    }

    // ---- epilogue ----
    const int tr = lane >> 2;
    const int tc2 = (lane & 3) * 2;
    #pragma unroll
    for (int mi = 0; mi < 4; mi++) {
        #pragma unroll
        for (int h2 = 0; h2 < 2; h2++) {
            int row = m0 + wm * 64 + mi * 16 + h2 * 8 + tr;
            float* crow = (MODE == 3) ? C + (size_t)row * ldc : nullptr;
            const float* rrow = (MODE == 3) ? aux + (size_t)row * ldr : nullptr;
            #pragma unroll
            for (int ni = 0; ni < 4; ni++) {
                int col = n0 + wn * 32 + ni * 8 + tc2;
                if (col < N) {
                    float v0 = acc[mi][ni][2 * h2];
                    float v1 = acc[mi][ni][2 * h2 + 1];
                    if (MODE == 1) {
                        v0 = gelu_tanh(v0 + bias[col]);
                        v1 = gelu_tanh(v1 + bias[col + 1]);
                        uint32_t hp, lp;
                        packsplit(v0, v1, hp, lp);
                        *(uint32_t*)(OH + (size_t)row * ldo + col) = hp;
                        *(uint32_t*)(OL + (size_t)row * ldo + col) = lp;
                    } else if (MODE == 3) {
                        v0 += bias[col] + rrow[col];
                        v1 += bias[col + 1] + rrow[col + 1];
                        *(float2*)(crow + col) = make_float2(v0, v1);
                    } else if (MODE == 4) {
                        v0 += bias[col];
                        v1 += bias[col + 1];
                        if (col < 2 * HIDD) {
                            int hd = (col % HIDD) % HDIM;
                            float2 cs = *(const float2*)(aux + (size_t)row * HDIM + hd);
                            float ra2 = v0 * cs.x - v1 * cs.y;
                            float rb2 = v0 * cs.y + v1 * cs.x;
                            v0 = ra2; v1 = rb2;
                        }
                        uint32_t hp, lp;
                        packsplit(v0, v1, hp, lp);
                        *(uint32_t*)(OH + (size_t)row * ldo + col) = hp;
                        *(uint32_t*)(OL + (size_t)row * ldo + col) = lp;
                    }
                }
            }
        }
    }
}

// ================= fused flash attention, double-buffered K/V =================
// smem: Qh,Ql (2 tiles) + 2 stages x {Kh,Kl,Vh,Vl} + 2 x segk.
#define VSTR   176
#define FTILE  (128 * VSTR)
#define KVOFF  (2 * FTILE)
#define STAGE4 (4 * FTILE)
#define SEGOFF (KVOFF + 2 * STAGE4)
#define FA_SMEM (SEGOFF + 1024)
#define ALPHA_ATT 0.11785113019775793f
#define NKT (SQ / 128)

__global__ void __launch_bounds__(256, 1)
flash_attn(const unsigned short* __restrict__ qkvh,
           const unsigned short* __restrict__ qkvl,
           const int* __restrict__ seg,
           unsigned short* __restrict__ atth,
           unsigned short* __restrict__ attl) {
    extern __shared__ char smf[];
    const int tid = threadIdx.x, lane = tid & 31, wid = tid >> 5;
    const int m0 = blockIdx.x * 128;
    const int hh = blockIdx.y;
    const int qcol = hh * HDIM;
    const uint32_t sb = smem_u32(smf);

    // ---- zero pad columns (bytes 144..159 of each row, all 10 tiles) ----
    {
        uint4 z = make_uint4(0, 0, 0, 0);
        #pragma unroll
        for (int i = 0; i < 5; i++) {
            int idx = tid + 256 * i;          // 0..1279
            int tile = idx >> 7, r = idx & 127;
            *(uint4*)(smf + (size_t)tile * FTILE + (size_t)r * VSTR + 144) = z;
        }
    }

    // ---- issue Q (group 0) and KV tile 0 (group 1) ----
    {
        #pragma unroll
        for (int i = 0; i < 9; i++) {
            int idx = tid + 256 * i;
            int tile = idx / 1152;
            int rem = idx - tile * 1152;
            int r = rem / 9, cc = rem - r * 9;
            const unsigned short* src = (tile ? qkvl : qkvh) + (size_t)(m0 + r) * T3 + qcol + cc * 8;
            cpasync16(sb + (uint32_t)tile * FTILE + (uint32_t)r * VSTR + cc * 16, src);
        }
        CP_COMMIT();
    }
    #define KV_ISSUE(kt_)  do {                                                       \
        int n0_ = (kt_) * 128;                                                        \
        uint32_t dstb_ = sb + KVOFF + (uint32_t)((kt_) & 1) * STAGE4;                 \
        const unsigned short* b0_ = qkvh + (size_t)n0_ * T3 + HIDD + qcol;            \
        const unsigned short* b1_ = qkvl + (size_t)n0_ * T3 + HIDD + qcol;            \
        const unsigned short* b2_ = b0_ + HIDD;                                       \
        const unsigned short* b3_ = b1_ + HIDD;                                       \
        _Pragma("unroll")                                                             \
        for (int i = 0; i < 18; i++) {                                                \
            int idx = tid + 256 * i;                                                  \
            int tile = idx / 1152;                                                    \
            int rem = idx - tile * 1152;                                              \
            int r = rem / 9, cc = rem - r * 9;                                        \
            const unsigned short* src =                                               \
                (tile == 0 ? b0_ : tile == 1 ? b1_ : tile == 2 ? b2_ : b3_)           \
                + (size_t)r * T3 + cc * 8;                                            \
            cpasync16(dstb_ + (uint32_t)tile * FTILE + (uint32_t)r * VSTR + cc * 16, src); \
        }                                                                             \
        if (tid < 128)                                                                \
            *(int*)(smf + SEGOFF + ((kt_) & 1) * 512 + tid * 4) = seg[n0_ + tid];     \
        CP_COMMIT();                                                                  \
    } while (0)

    KV_ISSUE(0);

    // ---- wait Q, load Q fragments ----
    CP_WAIT(1);
    __syncthreads();
    uint32_t qh[5][4], ql[5][4];
    {
        uint32_t qa = sb + (uint32_t)(wid * 16 + (lane & 15)) * VSTR + (lane >> 4) * 16;
        #pragma unroll
        for (int kc = 0; kc < 5; kc++) {
            ldsm4(qh[kc], qa + kc * 32);
            ldsm4(ql[kc], qa + kc * 32 + FTILE);
        }
    }

    const int tr = lane >> 2, tc = lane & 3;
    const int segq0 = seg[m0 + wid * 16 + tr];
    const int segq1 = seg[m0 + wid * 16 + tr + 8];

    float mr0 = -1e30f, mr1 = -1e30f;
    float el0 = 0.f, el1 = 0.f;
    float o[9][4];
    #pragma unroll
    for (int f = 0; f < 9; f++)
        #pragma unroll
        for (int e = 0; e < 4; e++) o[f][e] = 0.f;

    for (int kt = 0; kt < NKT; kt++) {
        __syncthreads();                    // buffer (kt+1)&1 free, segk writable
        if (kt + 1 < NKT) KV_ISSUE(kt + 1);
        if (kt == NKT - 1) { CP_WAIT(0); } else { CP_WAIT(1); }
        __syncthreads();

        const uint32_t kvb = sb + KVOFF + (uint32_t)(kt & 1) * STAGE4;
        const int* segk = (const int*)(smf + SEGOFF + (kt & 1) * 512);

        // ---- S = Q K^T (3-term) ----
        float s[16][4];
        #pragma unroll
        for (int ni = 0; ni < 16; ni++)
            #pragma unroll
            for (int e = 0; e < 4; e++) s[ni][e] = 0.f;

        #pragma unroll
        for (int kc = 0; kc < 5; kc++) {
            #pragma unroll
            for (int nj = 0; nj < 8; nj++) {
                uint32_t bh4[4], bl4[4];
                uint32_t kb = kvb + (uint32_t)(nj * 16 + ((lane >> 4) << 3) + (lane & 7)) * VSTR
                              + ((lane >> 3) & 1) * 16 + kc * 32;
                ldsm4(bh4, kb);
                ldsm4(bl4, kb + FTILE);
                mma16816(s[2 * nj],     qh[kc], bh4);
                mma16816(s[2 * nj],     qh[kc], bl4);
                mma16816(s[2 * nj],     ql[kc], bh4);
                mma16816(s[2 * nj + 1], qh[kc], bh4 + 2);
                mma16816(s[2 * nj + 1], qh[kc], bl4 + 2);
                mma16816(s[2 * nj + 1], ql[kc], bh4 + 2);
            }
        }

        // ---- alpha scale + segment bias + online softmax ----
        float rm0 = -1e30f, rm1 = -1e30f;
        #pragma unroll
        for (int ni = 0; ni < 16; ni++) {
            int sk0 = segk[ni * 8 + 2 * tc];
            int sk1 = segk[ni * 8 + 2 * tc + 1];
            s[ni][0] = fmaf(s[ni][0], ALPHA_ATT, (segq0 == sk0) ? 1.f : 0.f);
            s[ni][1] = fmaf(s[ni][1], ALPHA_ATT, (segq0 == sk1) ? 1.f : 0.f);
            s[ni][2] = fmaf(s[ni][2], ALPHA_ATT, (segq1 == sk0) ? 1.f : 0.f);
            s[ni][3] = fmaf(s[ni][3], ALPHA_ATT, (segq1 == sk1) ? 1.f : 0.f);
            rm0 = fmaxf(rm0, fmaxf(s[ni][0], s[ni][1]));
            rm1 = fmaxf(rm1, fmaxf(s[ni][2], s[ni][3]));
        }
        rm0 = fmaxf(rm0, __shfl_xor_sync(0xffffffffu, rm0, 1));
        rm0 = fmaxf(rm0, __shfl_xor_sync(0xffffffffu, rm0, 2));
        rm1 = fmaxf(rm1, __shfl_xor_sync(0xffffffffu, rm1, 1));
        rm1 = fmaxf(rm1, __shfl_xor_sync(0xffffffffu, rm1, 2));
        float mn0 = fmaxf(mr0, rm0), mn1 = fmaxf(mr1, rm1);
        float sc0 = __expf(mr0 - mn0), sc1 = __expf(mr1 - mn1);
        mr0 = mn0; mr1 = mn1;
        float rs0 = 0.f, rs1 = 0.f;
        #pragma unroll
        for (int ni = 0; ni < 16; ni++) {
            s[ni][0] = __expf(s[ni][0] - mn0); rs0 += s[ni][0];
            s[ni][1] = __expf(s[ni][1] - mn0); rs0 += s[ni][1];
            s[ni][2] = __expf(s[ni][2] - mn1); rs1 += s[ni][2];
            s[ni][3] = __expf(s[ni][3] - mn1); rs1 += s[ni][3];
        }
        rs0 += __shfl_xor_sync(0xffffffffu, rs0, 1);
        rs0 += __shfl_xor_sync(0xffffffffu, rs0, 2);
        rs1 += __shfl_xor_sync(0xffffffffu, rs1, 1);
        rs1 += __shfl_xor_sync(0xffffffffu, rs1, 2);
        el0 = el0 * sc0 + rs0;
        el1 = el1 * sc1 + rs1;
        #pragma unroll
        for (int f = 0; f < 9; f++) {
            o[f][0] *= sc0; o[f][1] *= sc0;
            o[f][2] *= sc1; o[f][3] *= sc1;
        }

        // ---- O += P V (3-term) ----
        #pragma unroll
        for (int kc2 = 0; kc2 < 8; kc2++) {
            uint32_t ph[4], pl[4];
            packsplit(s[2 * kc2][0],     s[2 * kc2][1],     ph[0], pl[0]);
            packsplit(s[2 * kc2][2],     s[2 * kc2][3],     ph[1], pl[1]);
            packsplit(s[2 * kc2 + 1][0], s[2 * kc2 + 1][1], ph[2], pl[2]);
            packsplit(s[2 * kc2 + 1][2], s[2 * kc2 + 1][3], ph[3], pl[3]);
            #pragma unroll
            for (int vj = 0; vj < 5; vj++) {
                uint32_t vh4[4], vl4[4];
                uint32_t va = kvb + 2 * FTILE
                              + (uint32_t)(kc2 * 16 + (lane & 15)) * VSTR
                              + (uint32_t)(vj * 16 + (lane >> 4) * 8) * 2;
                ldsm4t(vh4, va);
                ldsm4t(vl4, va + FTILE);
                mma16816(o[2 * vj], ph, vh4);
                mma16816(o[2 * vj], ph, vl4);
                mma16816(o[2 * vj], pl, vh4);
                if (vj < 4) {
                    mma16816(o[2 * vj + 1], ph, vh4 + 2);
                    mma16816(o[2 * vj + 1], ph, vl4 + 2);
                    mma16816(o[2 * vj + 1], pl, vh4 + 2);
                }
            }
        }
    }

    // ---- normalize, split, store bf16 hi/lo ----
    float i0 = 1.f / el0, i1 = 1.f / el1;
    int row0 = m0 + wid * 16 + tr;
    size_t ob0 = (size_t)row0 * HIDD + qcol;
    size_t ob1 = ob0 + (size_t)8 * HIDD;
    #pragma unroll
    for (int f = 0; f < 9; f++) {
        int col = f * 8 + 2 * tc;
        uint32_t hp, lp;
        packsplit(o[f][0] * i0, o[f][1] * i0, hp, lp);
        *(uint32_t*)(atth + ob0 + col) = hp;
        *(uint32_t*)(attl + ob0 + col) = lp;
        packsplit(o[f][2] * i1, o[f][3] * i1, hp, lp);
        *(uint32_t*)(atth + ob1 + col) = hp;
        *(uint32_t*)(attl + ob1 + col) = lp;
    }
    #undef KV_ISSUE
}

// ---------------- layernorm -> bf16 hi/lo ----------------
__global__ void ln_kernel(const float* __restrict__ x,
                          const float* __restrict__ g,
                          const float* __restrict__ b,
                          unsigned short* __restrict__ oh,
                          unsigned short* __restrict__ ol) {
    int row = blockIdx.x;
    const float* xr = x + (size_t)row * HIDD;
    float s1 = 0.f, s2 = 0.f;
    for (int i = threadIdx.x; i < HIDD; i += blockDim.x) {
        float v = xr[i];
        s1 += v; s2 += v * v;
    }
    __shared__ float sh1[8], sh2[8];
    #pragma unroll
    for (int o2 = 16; o2; o2 >>= 1) {
        s1 += __shfl_xor_sync(0xffffffffu, s1, o2);
        s2 += __shfl_xor_sync(0xffffffffu, s2, o2);
    }
    int w = threadIdx.x >> 5, l = threadIdx.x & 31;
    if (l == 0) { sh1[w] = s1; sh2[w] = s2; }
    __syncthreads();
    if (w == 0) {
        s1 = (l < 8) ? sh1[l] : 0.f;
        s2 = (l < 8) ? sh2[l] : 0.f;
        #pragma unroll
        for (int o2 = 4; o2; o2 >>= 1) {
            s1 += __shfl_xor_sync(0xffffffffu, s1, o2);
            s2 += __shfl_xor_sync(0xffffffffu, s2, o2);
        }
        if (l == 0) { sh1[0] = s1; sh2[0] = s2; }
    }
    __syncthreads();
    float mu = sh1[0] * (1.0f / HIDD);
    float var = sh2[0] * (1.0f / HIDD) - mu * mu;
    float rs = rsqrtf(var + EPSLN);
    for (int i = threadIdx.x; i < HIDD; i += blockDim.x) {
        float v = (xr[i] - mu) * rs * g[i] + b[i];
        unsigned short hv, lv;
        split_bf(v, hv, lv);
        oh[(size_t)row * HIDD + i] = hv;
        ol[(size_t)row * HIDD + i] = lv;
    }
}

// ---------------- segment ids ----------------
__global__ void seg_kernel(const int* __restrict__ off, int n, int* __restrict__ seg) {
    int t = blockIdx.x * blockDim.x + threadIdx.x;
    if (t >= SQ) return;
    int s = 0;
    for (int i = 1; i < n; i++)
        if (t >= off[i]) s = i;
    seg[t] = s;
}

// ---------------- launcher ----------------
extern "C" void kernel_launch(void* const* d_in, const int* in_sizes, int n_in,
                              void* d_out, int out_size) {
    const float* x      = (const float*)d_in[0];
    const int*   offs   = (const int*)d_in[1];
    const float* fc     = (const float*)d_in[2];
    const float* ln0_g  = (const float*)d_in[3];
    const float* ln0_b  = (const float*)d_in[4];
    const float* wqkv_w = (const float*)d_in[5];
    const float* wqkv_b = (const float*)d_in[6];
    const float* wo_w   = (const float*)d_in[7];
    const float* wo_b   = (const float*)d_in[8];
    const float* ln1_g  = (const float*)d_in[9];
    const float* ln1_b  = (const float*)d_in[10];
    const float* w1     = (const float*)d_in[11];
    const float* b1     = (const float*)d_in[12];
    const float* w2     = (const float*)d_in[13];
    const float* b2     = (const float*)d_in[14];
    float* out = (float*)d_out;

    unsigned short *hh, *hl, *qkvh, *qkvl, *atth, *attl, *mlph, *mlpl;
    unsigned short *wqt_h, *wqt_l, *wot_h, *wot_l, *w1t_h, *w1t_l, *w2t_h, *w2t_l;
    float *y1;
    int* seg;
    cudaGetSymbolAddress((void**)&hh, g_hh);
    cudaGetSymbolAddress((void**)&hl, g_hl);
    cudaGetSymbolAddress((void**)&qkvh, g_qkvh);
    cudaGetSymbolAddress((void**)&qkvl, g_qkvl);
    cudaGetSymbolAddress((void**)&atth, g_atth);
    cudaGetSymbolAddress((void**)&attl, g_attl);
    cudaGetSymbolAddress((void**)&y1, g_y1);
    cudaGetSymbolAddress((void**)&mlph, g_mlph);
    cudaGetSymbolAddress((void**)&mlpl, g_mlpl);
    cudaGetSymbolAddress((void**)&wqt_h, g_wqkvt_h);
    cudaGetSymbolAddress((void**)&wqt_l, g_wqkvt_l);
    cudaGetSymbolAddress((void**)&wot_h, g_wot_h);
    cudaGetSymbolAddress((void**)&wot_l, g_wot_l);
    cudaGetSymbolAddress((void**)&w1t_h, g_w1t_h);
    cudaGetSymbolAddress((void**)&w1t_l, g_w1t_l);
    cudaGetSymbolAddress((void**)&w2t_h, g_w2t_h);
    cudaGetSymbolAddress((void**)&w2t_l, g_w2t_l);
    cudaGetSymbolAddress((void**)&seg, g_seg);

    cudaFuncSetAttribute(gemm_bf<1>, cudaFuncAttributeMaxDynamicSharedMemorySize, GB_SMEM);
    cudaFuncSetAttribute(gemm_bf<3>, cudaFuncAttributeMaxDynamicSharedMemorySize, GB_SMEM);
    cudaFuncSetAttribute(gemm_bf<4>, cudaFuncAttributeMaxDynamicSharedMemorySize, GB_SMEM);
    cudaFuncSetAttribute(flash_attn, cudaFuncAttributeMaxDynamicSharedMemorySize, FA_SMEM);

    int n_off = in_sizes[1];
    dim3 ctb(32, 8);

    // 0. weight convert+transpose
    convtrans<<<dim3(T3 / 32, HIDD / 32), ctb>>>(wqkv_w, HIDD, T3, wqt_h, wqt_l, HIDD);
    convtrans<<<dim3(HIDD / 32, HIDD / 32), ctb>>>(wo_w, HIDD, HIDD, wot_h, wot_l, HIDD);
    convtrans<<<dim3((MLPD + 31) / 32, HIDD / 32), ctb>>>(w1, HIDD, MLPD, w1t_h, w1t_l, HIDD);
    convtrans<<<dim3(HIDD / 32, (MLPD + 31) / 32), ctb>>>(w2, MLPD, HIDD, w2t_h, w2t_l, MLPP);

    // 1. LN0 -> h (bf16 hi/lo)
    ln_kernel<<<SQ, 256>>>(x, ln0_g, ln0_b, hh, hl);

    // 2. segment ids
    seg_kernel<<<(SQ + 255) / 256, 256>>>(offs, n_off, seg);

    // 3. QKV = h @ Wqkv + b, fused RoPE + bf16 split -> qkvh/qkvl
    gemm_bf<4><<<dim3(T3 / 128, SQ / 128), 256, GB_SMEM>>>(
        T3, HIDD, hh, hl, wqt_h, wqt_l, nullptr, 0,
        qkvh, qkvl, T3, wqkv_b, fc, 0);

    // 4. fused attention -> att (bf16 hi/lo)
    flash_attn<<<dim3(SQ / 128, NHD), 256, FA_SMEM>>>(qkvh, qkvl, seg, atth, attl);

    // 5. y1 = x + att @ Wo + b
    gemm_bf<3><<<dim3(HIDD / 128, SQ / 128), 256, GB_SMEM>>>(
        HIDD, HIDD, atth, attl, wot_h, wot_l, y1, HIDD,
        nullptr, nullptr, 0, wo_b, x, HIDD);

    // 6. LN1 -> h (bf16 hi/lo)
    ln_kernel<<<SQ, 256>>>(y1, ln1_g, ln1_b, hh, hl);

    // 7. mlp = gelu(h @ W1 + b1) -> bf16 hi/lo (padded to 4352)
    gemm_bf<1><<<dim3(MLPP / 128, SQ / 128), 256, GB_SMEM>>>(
        MLPD, HIDD, hh, hl, w1t_h, w1t_l, nullptr, 0,
        mlph, mlpl, MLPP, b1, nullptr, 0);

    // 8. out = y1 + mlp @ W2 + b2
    gemm_bf<3><<<dim3(HIDD / 128, SQ / 128), 256, GB_SMEM>>>(
        HIDD, MLPP, mlph, mlpl, w2t_h, w2t_l, out, HIDD,
        nullptr, nullptr, 0, b2, y1, HIDD);
}